// round 1
// baseline (speedup 1.0000x reference)
#include <cuda_runtime.h>
#include <math.h>

// ---------------- problem constants (fixed by setup_inputs) ----------------
#define NB   2
#define NCH  128            // C
#define NH   128
#define NW   128
#define NE   6              // experts
#define ND   6
#define NHF  512            // hidden
#define NHW  (NH*NW)        // 16384
#define NTOK (NB*NH*NW)     // 32768
#define NOUT (NTOK*NCH)     // 4194304
#define GBLK 512            // gate-kernel blocks (64 tokens each)

// ---------------- scratch (static device globals; no allocs) ----------------
__device__ float g_xf[NTOK * NCH];            // 16 MB  token-major activations
__device__ float g_res[NTOK * 2 * NCH];       // 33.5MB per (token,k) expert output: gate*exp(out)
__device__ int   g_list[NE * NTOK];           // per-expert packed (token*2+k)
__device__ float g_gate[NE * NTOK];           // per-expert gate value
__device__ int   g_cnt[NE];
__device__ float g_bias[NB * NE];             // per-batch gate bias (prompt + degra part)
__device__ float g_partW[GBLK * NE];
__device__ float g_partC[GBLK * NE];

__device__ __forceinline__ float gelu_exact(float z) {
    return 0.5f * z * (1.0f + erff(z * 0.7071067811865475f));
}

// ---------------- kernel 1: tiny init (per-b gate bias, zero counters) ------
__global__ void k_init(const float* __restrict__ prompt,
                       const float* __restrict__ de_cls,
                       const float* __restrict__ w_g,
                       const float* __restrict__ gboost,
                       const float* __restrict__ degra_w,
                       const float* __restrict__ degra_b) {
    int t = threadIdx.x;
    if (t < NB * NE) {
        int b = t / NE, e = t % NE;
        float s1 = 0.f;
        for (int c = 0; c < NCH; c++)
            s1 += prompt[b * NCH + c] * w_g[(NCH + c) * NE + e];
        float s2 = 0.f;
        for (int d = 0; d < ND; d++)
            s2 += de_cls[b * ND + d] * degra_w[d * NE + e];
        g_bias[t] = s1 + gboost[0] * (s2 + degra_b[e]);
    }
    if (t < NE) g_cnt[t] = 0;
}

// ---------------- kernel 2: transpose x (B,C,H,W) -> xf[token][C] -----------
__global__ void k_trans(const float* __restrict__ x) {
    __shared__ float tile[32][33];
    int bh = blockIdx.z;
    int b = bh / NH, h = bh % NH;
    int c0 = blockIdx.x * 32, w0 = blockIdx.y * 32;
    int tx = threadIdx.x, ty = threadIdx.y;
    // tile[i][tx] = x[b, c0+i, h, w0+tx]
    for (int i = ty; i < 32; i += 8)
        tile[i][tx] = x[(((size_t)b * NCH + c0 + i) * NH + h) * NW + w0 + tx];
    __syncthreads();
    // xf[token(b,h,w0+i)][c0+tx] = tile[tx][i]
    for (int i = ty; i < 32; i += 8)
        g_xf[((size_t)(b * NHW + h * NW + w0 + i)) * NCH + c0 + tx] = tile[tx][i];
}

// ---------------- kernel 3: gating: logits, top2, scatter, partials ---------
__global__ void k_gate(const float* __restrict__ w_g) {
    __shared__ float wg_s[NCH * NE];   // first C rows of w_g (x part)
    __shared__ float wsum[2][NE];
    __shared__ int   wcnt[2][NE];
    int tid = threadIdx.x;
    for (int i = tid; i < NCH * NE; i += 64) wg_s[i] = w_g[i];
    __syncthreads();

    int n = blockIdx.x * 64 + tid;
    int b = n / NHW;
    float acc[NE];
#pragma unroll
    for (int e = 0; e < NE; e++) acc[e] = g_bias[b * NE + e];
    const float* xr = g_xf + (size_t)n * NCH;
#pragma unroll 4
    for (int c = 0; c < NCH; c++) {
        float xv = xr[c];
#pragma unroll
        for (int e = 0; e < NE; e++) acc[e] += xv * wg_s[c * NE + e];
    }
    // top-2 (ties -> lowest index, matches lax.top_k)
    int i0 = 0; float v0 = acc[0];
#pragma unroll
    for (int e = 1; e < NE; e++) if (acc[e] > v0) { v0 = acc[e]; i0 = e; }
    int i1 = (i0 == 0) ? 1 : 0; float v1 = acc[i1];
#pragma unroll
    for (int e = 0; e < NE; e++)
        if (e != i0 && acc[e] > v1) { v1 = acc[e]; i1 = e; }
    float g0 = 1.f / (1.f + expf(v1 - v0));
    float g1 = 1.f - g0;

    int p0 = atomicAdd(&g_cnt[i0], 1);
    g_list[i0 * NTOK + p0] = n * 2 + 0;
    g_gate[i0 * NTOK + p0] = g0;
    int p1 = atomicAdd(&g_cnt[i1], 1);
    g_list[i1 * NTOK + p1] = n * 2 + 1;
    g_gate[i1 * NTOK + p1] = g1;

    // deterministic per-block partial sums (fixed-order tree)
    int warp = tid >> 5, lane = tid & 31;
#pragma unroll
    for (int e = 0; e < NE; e++) {
        float gv = (i0 == e ? g0 : 0.f) + (i1 == e ? g1 : 0.f);
        int   cv = (i0 == e) + (i1 == e);
        for (int off = 16; off; off >>= 1) {
            gv += __shfl_down_sync(0xffffffffu, gv, off);
            cv += __shfl_down_sync(0xffffffffu, cv, off);
        }
        if (lane == 0) { wsum[warp][e] = gv; wcnt[warp][e] = cv; }
    }
    __syncthreads();
    if (tid < NE) {
        g_partW[blockIdx.x * NE + tid] = wsum[0][tid] + wsum[1][tid];
        g_partC[blockIdx.x * NE + tid] = (float)(wcnt[0][tid] + wcnt[1][tid]);
    }
}

// ---------------- kernel 4: loss reduction ----------------------------------
__global__ void k_loss(float* __restrict__ out, int out_size) {
    __shared__ float red[512];
    __shared__ float Wv[NE], Cv[NE];
    int tid = threadIdx.x;
    for (int e = 0; e < NE; e++) {
        red[tid] = g_partW[tid * NE + e];
        __syncthreads();
        for (int s = 256; s; s >>= 1) { if (tid < s) red[tid] += red[tid + s]; __syncthreads(); }
        if (tid == 0) Wv[e] = red[0];
        __syncthreads();
        red[tid] = g_partC[tid * NE + e];
        __syncthreads();
        for (int s = 256; s; s >>= 1) { if (tid < s) red[tid] += red[tid + s]; __syncthreads(); }
        if (tid == 0) Cv[e] = red[0];
        __syncthreads();
    }
    if (tid == 0 && out_size > NOUT) {
        float mW = 0.f, mC = 0.f;
        for (int e = 0; e < NE; e++) { mW += Wv[e]; mC += Cv[e]; }
        mW /= NE; mC /= NE;
        float vW = 0.f, vC = 0.f;
        for (int e = 0; e < NE; e++) {
            vW += (Wv[e] - mW) * (Wv[e] - mW);
            vC += (Cv[e] - mC) * (Cv[e] - mC);
        }
        vW /= (NE - 1); vC /= (NE - 1);
        out[NOUT] = vW / (mW * mW + 1e-10f) + vC / (mC * mC + 1e-10f);
    }
}

// ---------------- kernel 5: grouped fused expert MLP ------------------------
// tile: 64 (token,k) entries of one expert; HF chunked by 64.
// smem layout (dynamic):
struct MoeSmem {
    float Xs[64][132];      // gathered X tile (padded: bank-safe, 16B aligned rows)
    float Ws[64 * 128];     // W1 chunk [128][64] or W2 chunk [64][128]
    float Hs[64][68];       // gelu(hidden) chunk (padded)
    int   slot[64];
    float gate[64];
};
#define MOE_SMEM_BYTES (sizeof(MoeSmem))

__global__ void __launch_bounds__(256, 2)
k_moe(const float* __restrict__ fc1w, const float* __restrict__ fc1b,
      const float* __restrict__ fc2w, const float* __restrict__ fc2b) {
    int e    = blockIdx.x >> 9;         // /512
    int tile = blockIdx.x & 511;
    int cnt  = g_cnt[e];
    int row0 = tile * 64;
    if (row0 >= cnt) return;
    int mrows = min(64, cnt - row0);

    extern __shared__ char smem_raw[];
    MoeSmem& S = *reinterpret_cast<MoeSmem*>(smem_raw);

    int tid = threadIdx.x;
    int tx = tid & 15, ty = tid >> 4;   // 16x16

    if (tid < 64) {
        if (tid < mrows) {
            S.slot[tid] = g_list[e * NTOK + row0 + tid];
            S.gate[tid] = g_gate[e * NTOK + row0 + tid];
        } else {
            S.slot[tid] = -1;
            S.gate[tid] = 0.f;
        }
    }
    __syncthreads();

    // gather X rows (zero-pad invalid rows)
#pragma unroll
    for (int it = 0; it < 8; it++) {
        int idx = tid + it * 256;          // 0..2047
        int r = idx >> 5, c4 = idx & 31;
        float4 v = make_float4(0.f, 0.f, 0.f, 0.f);
        int s = S.slot[r];
        if (s >= 0) {
            int tok = s >> 1;
            v = *(const float4*)(g_xf + (size_t)tok * NCH + c4 * 4);
        }
        *(float4*)(&S.Xs[r][c4 * 4]) = v;
    }

    const float* w1 = fc1w + (size_t)e * NCH * NHF;
    const float* w2 = fc2w + (size_t)e * NHF * NCH;

    float acc2[4][8];
#pragma unroll
    for (int i = 0; i < 4; i++)
#pragma unroll
        for (int j = 0; j < 8; j++) acc2[i][j] = 0.f;

    for (int jc = 0; jc < 8; jc++) {        // 8 chunks of 64 over HF
        __syncthreads();                    // protect Ws / Hs from prior readers
        // load W1 chunk: [c=128][h=64]
#pragma unroll
        for (int it = 0; it < 8; it++) {
            int idx = tid + it * 256;
            int c = idx >> 4, h4 = idx & 15;
            *(float4*)(&S.Ws[c * 64 + h4 * 4]) =
                *(const float4*)(w1 + (size_t)c * NHF + jc * 64 + h4 * 4);
        }
        __syncthreads();

        float acc1[4][4];
#pragma unroll
        for (int i = 0; i < 4; i++)
#pragma unroll
            for (int j = 0; j < 4; j++) acc1[i][j] = 0.f;

#pragma unroll 4
        for (int k = 0; k < 128; k++) {
            float4 bv = *(float4*)(&S.Ws[k * 64 + tx * 4]);
#pragma unroll
            for (int i = 0; i < 4; i++) {
                float a = S.Xs[ty * 4 + i][k];
                acc1[i][0] += a * bv.x;
                acc1[i][1] += a * bv.y;
                acc1[i][2] += a * bv.z;
                acc1[i][3] += a * bv.w;
            }
        }
        // bias + exact gelu -> Hs
        float4 b1 = *(const float4*)(fc1b + e * NHF + jc * 64 + tx * 4);
#pragma unroll
        for (int i = 0; i < 4; i++) {
            float4 hv;
            hv.x = gelu_exact(acc1[i][0] + b1.x);
            hv.y = gelu_exact(acc1[i][1] + b1.y);
            hv.z = gelu_exact(acc1[i][2] + b1.z);
            hv.w = gelu_exact(acc1[i][3] + b1.w);
            *(float4*)(&S.Hs[ty * 4 + i][tx * 4]) = hv;
        }
        __syncthreads();
        // load W2 chunk: [h=64][c=128]
#pragma unroll
        for (int it = 0; it < 8; it++) {
            int idx = tid + it * 256;
            int h = idx >> 5, c4 = idx & 31;
            *(float4*)(&S.Ws[h * 128 + c4 * 4]) =
                *(const float4*)(w2 + (size_t)(jc * 64 + h) * NCH + c4 * 4);
        }
        __syncthreads();

#pragma unroll 2
        for (int k = 0; k < 64; k++) {
            float4 b0 = *(float4*)(&S.Ws[k * 128 + tx * 4]);
            float4 b4 = *(float4*)(&S.Ws[k * 128 + 64 + tx * 4]);
#pragma unroll
            for (int i = 0; i < 4; i++) {
                float a = S.Hs[ty * 4 + i][k];
                acc2[i][0] += a * b0.x;
                acc2[i][1] += a * b0.y;
                acc2[i][2] += a * b0.z;
                acc2[i][3] += a * b0.w;
                acc2[i][4] += a * b4.x;
                acc2[i][5] += a * b4.y;
                acc2[i][6] += a * b4.z;
                acc2[i][7] += a * b4.w;
            }
        }
    }

    // epilogue: res[slot][c] = gate * exp(out + fc2_b)
    float4 c0b = *(const float4*)(fc2b + e * NCH + tx * 4);
    float4 c4b = *(const float4*)(fc2b + e * NCH + 64 + tx * 4);
#pragma unroll
    for (int i = 0; i < 4; i++) {
        int r = ty * 4 + i;
        int s = S.slot[r];
        if (s < 0) continue;
        float g = S.gate[r];
        float* dst = g_res + (size_t)s * NCH;
        float4 o0, o4;
        o0.x = g * expf(acc2[i][0] + c0b.x);
        o0.y = g * expf(acc2[i][1] + c0b.y);
        o0.z = g * expf(acc2[i][2] + c0b.z);
        o0.w = g * expf(acc2[i][3] + c0b.w);
        o4.x = g * expf(acc2[i][4] + c4b.x);
        o4.y = g * expf(acc2[i][5] + c4b.y);
        o4.z = g * expf(acc2[i][6] + c4b.z);
        o4.w = g * expf(acc2[i][7] + c4b.w);
        *(float4*)(dst + tx * 4) = o0;
        *(float4*)(dst + 64 + tx * 4) = o4;
    }
}

// ---------------- kernel 6: combine + log + transpose back ------------------
__global__ void k_out(float* __restrict__ out) {
    __shared__ float tile[32][33];
    int bh = blockIdx.z;
    int b = bh / NH, h = bh % NH;
    int c0 = blockIdx.x * 32, w0 = blockIdx.y * 32;
    int tx = threadIdx.x, ty = threadIdx.y;
    for (int i = ty; i < 32; i += 8) {
        size_t base = (size_t)(b * NHW + h * NW + w0 + i) * 2 * NCH;
        float v = g_res[base + c0 + tx] + g_res[base + NCH + c0 + tx];
        if (v == 0.f) v = 2.2204460492503131e-16f;   // EPS_LOG guard
        tile[i][tx] = logf(v);
    }
    __syncthreads();
    for (int i = ty; i < 32; i += 8)
        out[(((size_t)b * NCH + c0 + i) * NH + h) * NW + w0 + tx] = tile[tx][i];
}

// ---------------- launch -----------------------------------------------------
extern "C" void kernel_launch(void* const* d_in, const int* in_sizes, int n_in,
                              void* d_out, int out_size) {
    (void)in_sizes; (void)n_in;
    const float* x       = (const float*)d_in[0];
    const float* prompt  = (const float*)d_in[1];
    const float* de_cls  = (const float*)d_in[2];
    const float* w_g     = (const float*)d_in[3];
    const float* gboost  = (const float*)d_in[4];
    const float* degra_w = (const float*)d_in[5];
    const float* degra_b = (const float*)d_in[6];
    const float* fc1w    = (const float*)d_in[7];
    const float* fc1b    = (const float*)d_in[8];
    const float* fc2w    = (const float*)d_in[9];
    const float* fc2b    = (const float*)d_in[10];
    float* out = (float*)d_out;

    k_init<<<1, 32>>>(prompt, de_cls, w_g, gboost, degra_w, degra_b);

    dim3 tb(32, 8);
    k_trans<<<dim3(NCH / 32, NW / 32, NB * NH), tb>>>(x);

    k_gate<<<GBLK, 64>>>(w_g);
    k_loss<<<1, 512>>>(out, out_size);

    cudaFuncSetAttribute(k_moe, cudaFuncAttributeMaxDynamicSharedMemorySize,
                         (int)MOE_SMEM_BYTES);
    k_moe<<<NE * 512, 256, MOE_SMEM_BYTES>>>(fc1w, fc1b, fc2w, fc2b);

    k_out<<<dim3(NCH / 32, NW / 32, NB * NH), tb>>>(out);
}

// round 3
// speedup vs baseline: 1.9620x; 1.9620x over previous
#include <cuda_runtime.h>
#include <cuda_bf16.h>
#include <math.h>

// ---------------- problem constants (fixed by setup_inputs) ----------------
#define NB   2
#define NCH  128            // C
#define NH   128
#define NW   128
#define NE   6              // experts
#define ND   6
#define NHF  512            // hidden
#define NHW  (NH*NW)        // 16384
#define NTOK (NB*NH*NW)     // 32768
#define NOUT (NTOK*NCH)     // 4194304
#define GBLK 512            // gate-kernel blocks (64 tokens each)

// ---------------- scratch (static device globals; no allocs) ----------------
__device__ float g_xf[NTOK * NCH];            // 16 MB  token-major activations
__device__ float g_res[NTOK * 2 * NCH];       // 33.5MB per (token,k): gate*exp(out)
__device__ int   g_list[NE * NTOK];           // per-expert packed (token*2+k)
__device__ float g_gate[NE * NTOK];
__device__ int   g_cnt[NE];
__device__ float g_bias[NB * NE];
__device__ float g_partW[GBLK * NE];
__device__ float g_partC[GBLK * NE];

// pre-split weights (bf16 hi/lo), B-operand layout [n][k] (k contiguous)
// w1t: [e][n=512 hf][k=128 c]    w2t: [e][jc=8][n=128 c][k=64 hf]
__device__ __align__(16) __nv_bfloat16 g_w1t_hi[NE * NHF * NCH];
__device__ __align__(16) __nv_bfloat16 g_w1t_lo[NE * NHF * NCH];
__device__ __align__(16) __nv_bfloat16 g_w2t_hi[NE * NHF * NCH];
__device__ __align__(16) __nv_bfloat16 g_w2t_lo[NE * NHF * NCH];

__device__ __forceinline__ float gelu_exact(float z) {
    return 0.5f * z * (1.0f + erff(z * 0.7071067811865475f));
}
__device__ __forceinline__ void split2(float a0, float a1, unsigned& hi, unsigned& lo) {
    __nv_bfloat16 h0 = __float2bfloat16_rn(a0);
    __nv_bfloat16 h1 = __float2bfloat16_rn(a1);
    __nv_bfloat16 l0 = __float2bfloat16_rn(a0 - __bfloat162float(h0));
    __nv_bfloat16 l1 = __float2bfloat16_rn(a1 - __bfloat162float(h1));
    hi = ((unsigned)__bfloat16_as_ushort(h1) << 16) | __bfloat16_as_ushort(h0);
    lo = ((unsigned)__bfloat16_as_ushort(l1) << 16) | __bfloat16_as_ushort(l0);
}
__device__ __forceinline__ void mma16816(float* c, const unsigned* a, const unsigned* b) {
    asm volatile("mma.sync.aligned.m16n8k16.row.col.f32.bf16.bf16.f32 "
                 "{%0,%1,%2,%3}, {%4,%5,%6,%7}, {%8,%9}, {%0,%1,%2,%3};"
                 : "+f"(c[0]), "+f"(c[1]), "+f"(c[2]), "+f"(c[3])
                 : "r"(a[0]), "r"(a[1]), "r"(a[2]), "r"(a[3]),
                   "r"(b[0]), "r"(b[1]));
}

// ---------------- kernel 1: tiny init ----------------------------------------
__global__ void k_init(const float* __restrict__ prompt,
                       const float* __restrict__ de_cls,
                       const float* __restrict__ w_g,
                       const float* __restrict__ gboost,
                       const float* __restrict__ degra_w,
                       const float* __restrict__ degra_b) {
    int t = threadIdx.x;
    if (t < NB * NE) {
        int b = t / NE, e = t % NE;
        float s1 = 0.f;
        for (int c = 0; c < NCH; c++)
            s1 += prompt[b * NCH + c] * w_g[(NCH + c) * NE + e];
        float s2 = 0.f;
        for (int d = 0; d < ND; d++)
            s2 += de_cls[b * ND + d] * degra_w[d * NE + e];
        g_bias[t] = s1 + gboost[0] * (s2 + degra_b[e]);
    }
    if (t < NE) g_cnt[t] = 0;
}

// ---------------- kernel 2: transpose x -> xf --------------------------------
__global__ void k_trans(const float* __restrict__ x) {
    __shared__ float tile[32][33];
    int bh = blockIdx.z;
    int b = bh / NH, h = bh % NH;
    int c0 = blockIdx.x * 32, w0 = blockIdx.y * 32;
    int tx = threadIdx.x, ty = threadIdx.y;
    for (int i = ty; i < 32; i += 8)
        tile[i][tx] = x[(((size_t)b * NCH + c0 + i) * NH + h) * NW + w0 + tx];
    __syncthreads();
    for (int i = ty; i < 32; i += 8)
        g_xf[((size_t)(b * NHW + h * NW + w0 + i)) * NCH + c0 + tx] = tile[tx][i];
}

// ---------------- kernel 3: gating -------------------------------------------
__global__ void k_gate(const float* __restrict__ w_g) {
    __shared__ float wg_s[NCH * NE];
    __shared__ float wsum[2][NE];
    __shared__ int   wcnt[2][NE];
    int tid = threadIdx.x;
    for (int i = tid; i < NCH * NE; i += 64) wg_s[i] = w_g[i];
    __syncthreads();

    int n = blockIdx.x * 64 + tid;
    int b = n / NHW;
    float acc[NE];
#pragma unroll
    for (int e = 0; e < NE; e++) acc[e] = g_bias[b * NE + e];
    const float* xr = g_xf + (size_t)n * NCH;
#pragma unroll 4
    for (int c = 0; c < NCH; c++) {
        float xv = xr[c];
#pragma unroll
        for (int e = 0; e < NE; e++) acc[e] += xv * wg_s[c * NE + e];
    }
    int i0 = 0; float v0 = acc[0];
#pragma unroll
    for (int e = 1; e < NE; e++) if (acc[e] > v0) { v0 = acc[e]; i0 = e; }
    int i1 = (i0 == 0) ? 1 : 0; float v1 = acc[i1];
#pragma unroll
    for (int e = 0; e < NE; e++)
        if (e != i0 && acc[e] > v1) { v1 = acc[e]; i1 = e; }
    float g0 = 1.f / (1.f + expf(v1 - v0));
    float g1 = 1.f - g0;

    int p0 = atomicAdd(&g_cnt[i0], 1);
    g_list[i0 * NTOK + p0] = n * 2 + 0;
    g_gate[i0 * NTOK + p0] = g0;
    int p1 = atomicAdd(&g_cnt[i1], 1);
    g_list[i1 * NTOK + p1] = n * 2 + 1;
    g_gate[i1 * NTOK + p1] = g1;

    int warp = tid >> 5, lane = tid & 31;
#pragma unroll
    for (int e = 0; e < NE; e++) {
        float gv = (i0 == e ? g0 : 0.f) + (i1 == e ? g1 : 0.f);
        int   cv = (i0 == e) + (i1 == e);
        for (int off = 16; off; off >>= 1) {
            gv += __shfl_down_sync(0xffffffffu, gv, off);
            cv += __shfl_down_sync(0xffffffffu, cv, off);
        }
        if (lane == 0) { wsum[warp][e] = gv; wcnt[warp][e] = cv; }
    }
    __syncthreads();
    if (tid < NE) {
        g_partW[blockIdx.x * NE + tid] = wsum[0][tid] + wsum[1][tid];
        g_partC[blockIdx.x * NE + tid] = (float)(wcnt[0][tid] + wcnt[1][tid]);
    }
}

// ---------------- kernel 4: loss reduction -----------------------------------
__global__ void k_loss(float* __restrict__ out, int out_size) {
    __shared__ float red[512];
    __shared__ float Wv[NE], Cv[NE];
    int tid = threadIdx.x;
    for (int e = 0; e < NE; e++) {
        red[tid] = g_partW[tid * NE + e];
        __syncthreads();
        for (int s = 256; s; s >>= 1) { if (tid < s) red[tid] += red[tid + s]; __syncthreads(); }
        if (tid == 0) Wv[e] = red[0];
        __syncthreads();
        red[tid] = g_partC[tid * NE + e];
        __syncthreads();
        for (int s = 256; s; s >>= 1) { if (tid < s) red[tid] += red[tid + s]; __syncthreads(); }
        if (tid == 0) Cv[e] = red[0];
        __syncthreads();
    }
    if (tid == 0 && out_size > NOUT) {
        float mW = 0.f, mC = 0.f;
        for (int e = 0; e < NE; e++) { mW += Wv[e]; mC += Cv[e]; }
        mW /= NE; mC /= NE;
        float vW = 0.f, vC = 0.f;
        for (int e = 0; e < NE; e++) {
            vW += (Wv[e] - mW) * (Wv[e] - mW);
            vC += (Cv[e] - mC) * (Cv[e] - mC);
        }
        vW /= (NE - 1); vC /= (NE - 1);
        out[NOUT] = vW / (mW * mW + 1e-10f) + vC / (mC * mC + 1e-10f);
    }
}

// ---------------- kernel 4b: weight prep (split + transpose to [n][k]) -------
#define W1ELEM (NE * NHF * NCH)   // 393216
__global__ void k_prep(const float* __restrict__ fc1w, const float* __restrict__ fc2w) {
    int idx = blockIdx.x * 256 + threadIdx.x;
    if (idx < W1ELEM) {
        int e = idx >> 16, rem = idx & 65535;
        int n = rem >> 7, k = rem & 127;        // n: hf, k: c
        float v = fc1w[((size_t)e * NCH + k) * NHF + n];
        __nv_bfloat16 h = __float2bfloat16_rn(v);
        g_w1t_hi[idx] = h;
        g_w1t_lo[idx] = __float2bfloat16_rn(v - __bfloat162float(h));
    } else {
        int j = idx - W1ELEM;
        if (j < W1ELEM) {
            int e = j >> 16, rem = j & 65535;
            int jc = rem >> 13, r2 = rem & 8191;
            int c = r2 >> 6, k = r2 & 63;       // n: c, k: hf within chunk
            float v = fc2w[((size_t)e * NHF + jc * 64 + k) * NCH + c];
            __nv_bfloat16 h = __float2bfloat16_rn(v);
            g_w2t_hi[j] = h;
            g_w2t_lo[j] = __float2bfloat16_rn(v - __bfloat162float(h));
        }
    }
}

// ---------------- kernel 5: mma.sync grouped expert MLP ----------------------
// SMEM byte offsets (element strides: X=136, W1=136, H=72, W2=72)
#define S2_XH   0          // [128][136] bf16 = 34816
#define S2_XL   34816
#define S2_W1H  69632      // [64][136]  bf16 = 17408
#define S2_W1L  87040
#define S2_HH   104448     // [128][72]  bf16 = 18432
#define S2_HL   122880
#define S2_W2H  141312     // [128][72]  bf16 = 18432
#define S2_W2L  159744
#define S2_SLOT 178176     // 128 int
#define S2_GATE 178688     // 128 float
#define S2_BYTES 179200

__global__ void __launch_bounds__(256, 1)
k_moe(const float* __restrict__ fc1b, const float* __restrict__ fc2b) {
    int e    = blockIdx.x >> 9;
    int tile = blockIdx.x & 511;
    int cnt  = g_cnt[e];
    int row0 = tile << 7;
    if (row0 >= cnt) return;

    extern __shared__ char sm[];
    __nv_bfloat16* Xh  = (__nv_bfloat16*)(sm + S2_XH);
    __nv_bfloat16* Xl  = (__nv_bfloat16*)(sm + S2_XL);
    __nv_bfloat16* W1h = (__nv_bfloat16*)(sm + S2_W1H);
    __nv_bfloat16* W1l = (__nv_bfloat16*)(sm + S2_W1L);
    __nv_bfloat16* Hh  = (__nv_bfloat16*)(sm + S2_HH);
    __nv_bfloat16* Hl  = (__nv_bfloat16*)(sm + S2_HL);
    __nv_bfloat16* W2h = (__nv_bfloat16*)(sm + S2_W2H);
    __nv_bfloat16* W2l = (__nv_bfloat16*)(sm + S2_W2L);
    int*   slot_s = (int*)(sm + S2_SLOT);
    float* gate_s = (float*)(sm + S2_GATE);

    int tid = threadIdx.x;
    int wid = tid >> 5, lt = tid & 31;
    int qr = lt >> 2, qc = lt & 3;          // quad row / quad col
    int m0 = wid * 16;

    if (tid < 128) {
        int r = row0 + tid;
        if (r < cnt) { slot_s[tid] = g_list[e * NTOK + r]; gate_s[tid] = g_gate[e * NTOK + r]; }
        else         { slot_s[tid] = -1; gate_s[tid] = 0.f; }
    }
    __syncthreads();

    // gather X -> split bf16 (padded rows of 136)
#pragma unroll
    for (int it = 0; it < 8; it++) {
        int idx = tid + it * 256;
        int r = idx >> 4, c8 = idx & 15;
        float v[8];
        int s = slot_s[r];
        if (s >= 0) {
            const float4* src = (const float4*)(g_xf + (size_t)(s >> 1) * NCH + c8 * 8);
            float4 a = src[0], b = src[1];
            v[0]=a.x; v[1]=a.y; v[2]=a.z; v[3]=a.w; v[4]=b.x; v[5]=b.y; v[6]=b.z; v[7]=b.w;
        } else {
#pragma unroll
            for (int q = 0; q < 8; q++) v[q] = 0.f;
        }
        uint4 Uh, Ul;
        split2(v[0], v[1], Uh.x, Ul.x);
        split2(v[2], v[3], Uh.y, Ul.y);
        split2(v[4], v[5], Uh.z, Ul.z);
        split2(v[6], v[7], Uh.w, Ul.w);
        *(uint4*)(Xh + r * 136 + c8 * 8) = Uh;
        *(uint4*)(Xl + r * 136 + c8 * 8) = Ul;
    }

    float acc2[16][4];
#pragma unroll
    for (int j = 0; j < 16; j++)
#pragma unroll
        for (int q = 0; q < 4; q++) acc2[j][q] = 0.f;

    for (int jc = 0; jc < 8; jc++) {
        // load W1 chunk [64 hf][128 c] and W2 chunk [128 c][64 hf] (hi+lo)
        {
            const uint4* s1h = (const uint4*)(g_w1t_hi + ((size_t)e * NHF + jc * 64) * NCH);
            const uint4* s1l = (const uint4*)(g_w1t_lo + ((size_t)e * NHF + jc * 64) * NCH);
            const uint4* s2h = (const uint4*)(g_w2t_hi + ((size_t)e * 8 + jc) * 8192);
            const uint4* s2l = (const uint4*)(g_w2t_lo + ((size_t)e * 8 + jc) * 8192);
#pragma unroll
            for (int it = 0; it < 4; it++) {
                int u = tid + it * 256;          // 0..1023
                int n1 = u >> 4, k16 = u & 15;
                *(uint4*)(W1h + n1 * 136 + k16 * 8) = s1h[u];
                *(uint4*)(W1l + n1 * 136 + k16 * 8) = s1l[u];
                int n2 = u >> 3, k8 = u & 7;
                *(uint4*)(W2h + n2 * 72 + k8 * 8) = s2h[u];
                *(uint4*)(W2l + n2 * 72 + k8 * 8) = s2l[u];
            }
        }
        __syncthreads();

        // GEMM1: [128 x 64] = X[128 x 128] * W1^T, 3-pass split
        float acc1[8][4];
#pragma unroll
        for (int j = 0; j < 8; j++)
#pragma unroll
            for (int q = 0; q < 4; q++) acc1[j][q] = 0.f;

#pragma unroll
        for (int kt = 0; kt < 8; kt++) {
            int row = m0 + qr, col = kt * 16 + qc * 2;
            unsigned ah[4], al[4];
            ah[0] = *(const unsigned*)(Xh + row * 136 + col);
            ah[1] = *(const unsigned*)(Xh + (row + 8) * 136 + col);
            ah[2] = *(const unsigned*)(Xh + row * 136 + col + 8);
            ah[3] = *(const unsigned*)(Xh + (row + 8) * 136 + col + 8);
            al[0] = *(const unsigned*)(Xl + row * 136 + col);
            al[1] = *(const unsigned*)(Xl + (row + 8) * 136 + col);
            al[2] = *(const unsigned*)(Xl + row * 136 + col + 8);
            al[3] = *(const unsigned*)(Xl + (row + 8) * 136 + col + 8);
#pragma unroll
            for (int j = 0; j < 8; j++) {
                int n = j * 8 + qr;
                unsigned bh[2], bl[2];
                bh[0] = *(const unsigned*)(W1h + n * 136 + col);
                bh[1] = *(const unsigned*)(W1h + n * 136 + col + 8);
                bl[0] = *(const unsigned*)(W1l + n * 136 + col);
                bl[1] = *(const unsigned*)(W1l + n * 136 + col + 8);
                mma16816(acc1[j], ah, bh);
                mma16816(acc1[j], ah, bl);
                mma16816(acc1[j], al, bh);
            }
        }

        // bias + gelu -> H (split bf16)
#pragma unroll
        for (int j = 0; j < 8; j++) {
            int n = j * 8 + qc * 2;
            float2 b1 = *(const float2*)(fc1b + e * NHF + jc * 64 + n);
            float h0 = gelu_exact(acc1[j][0] + b1.x);
            float h1 = gelu_exact(acc1[j][1] + b1.y);
            float h2 = gelu_exact(acc1[j][2] + b1.x);
            float h3 = gelu_exact(acc1[j][3] + b1.y);
            unsigned hi, lo;
            split2(h0, h1, hi, lo);
            *(unsigned*)(Hh + (m0 + qr) * 72 + n) = hi;
            *(unsigned*)(Hl + (m0 + qr) * 72 + n) = lo;
            split2(h2, h3, hi, lo);
            *(unsigned*)(Hh + (m0 + qr + 8) * 72 + n) = hi;
            *(unsigned*)(Hl + (m0 + qr + 8) * 72 + n) = lo;
        }
        __syncthreads();

        // GEMM2: [128 x 128] += H[128 x 64] * W2^T, 3-pass split
#pragma unroll
        for (int kt = 0; kt < 4; kt++) {
            int row = m0 + qr, col = kt * 16 + qc * 2;
            unsigned ah[4], al[4];
            ah[0] = *(const unsigned*)(Hh + row * 72 + col);
            ah[1] = *(const unsigned*)(Hh + (row + 8) * 72 + col);
            ah[2] = *(const unsigned*)(Hh + row * 72 + col + 8);
            ah[3] = *(const unsigned*)(Hh + (row + 8) * 72 + col + 8);
            al[0] = *(const unsigned*)(Hl + row * 72 + col);
            al[1] = *(const unsigned*)(Hl + (row + 8) * 72 + col);
            al[2] = *(const unsigned*)(Hl + row * 72 + col + 8);
            al[3] = *(const unsigned*)(Hl + (row + 8) * 72 + col + 8);
#pragma unroll
            for (int j = 0; j < 16; j++) {
                int n = j * 8 + qr;
                unsigned bh[2], bl[2];
                bh[0] = *(const unsigned*)(W2h + n * 72 + col);
                bh[1] = *(const unsigned*)(W2h + n * 72 + col + 8);
                bl[0] = *(const unsigned*)(W2l + n * 72 + col);
                bl[1] = *(const unsigned*)(W2l + n * 72 + col + 8);
                mma16816(acc2[j], ah, bh);
                mma16816(acc2[j], ah, bl);
                mma16816(acc2[j], al, bh);
            }
        }
        __syncthreads();
    }

    // final epilogue: gate * exp(out + b2) -> g_res
    int mA = m0 + qr, mB = m0 + qr + 8;
    int sA = slot_s[mA], sB = slot_s[mB];
    float gA = gate_s[mA], gB = gate_s[mB];
#pragma unroll
    for (int j = 0; j < 16; j++) {
        int c = j * 8 + qc * 2;
        float2 b2 = *(const float2*)(fc2b + e * NCH + c);
        if (sA >= 0) {
            float2 o;
            o.x = gA * expf(acc2[j][0] + b2.x);
            o.y = gA * expf(acc2[j][1] + b2.y);
            *(float2*)(g_res + (size_t)sA * NCH + c) = o;
        }
        if (sB >= 0) {
            float2 o;
            o.x = gB * expf(acc2[j][2] + b2.x);
            o.y = gB * expf(acc2[j][3] + b2.y);
            *(float2*)(g_res + (size_t)sB * NCH + c) = o;
        }
    }
}

// ---------------- kernel 6: combine + log + transpose back --------------------
__global__ void k_out(float* __restrict__ out) {
    __shared__ float tile[32][33];
    int bh = blockIdx.z;
    int b = bh / NH, h = bh % NH;
    int c0 = blockIdx.x * 32, w0 = blockIdx.y * 32;
    int tx = threadIdx.x, ty = threadIdx.y;
    for (int i = ty; i < 32; i += 8) {
        size_t base = (size_t)(b * NHW + h * NW + w0 + i) * 2 * NCH;
        float v = g_res[base + c0 + tx] + g_res[base + NCH + c0 + tx];
        if (v == 0.f) v = 2.2204460492503131e-16f;
        tile[i][tx] = logf(v);
    }
    __syncthreads();
    for (int i = ty; i < 32; i += 8)
        out[(((size_t)b * NCH + c0 + i) * NH + h) * NW + w0 + tx] = tile[tx][i];
}

// ---------------- launch ------------------------------------------------------
extern "C" void kernel_launch(void* const* d_in, const int* in_sizes, int n_in,
                              void* d_out, int out_size) {
    (void)in_sizes; (void)n_in;
    const float* x       = (const float*)d_in[0];
    const float* prompt  = (const float*)d_in[1];
    const float* de_cls  = (const float*)d_in[2];
    const float* w_g     = (const float*)d_in[3];
    const float* gboost  = (const float*)d_in[4];
    const float* degra_w = (const float*)d_in[5];
    const float* degra_b = (const float*)d_in[6];
    const float* fc1w    = (const float*)d_in[7];
    const float* fc1b    = (const float*)d_in[8];
    const float* fc2w    = (const float*)d_in[9];
    const float* fc2b    = (const float*)d_in[10];
    float* out = (float*)d_out;

    k_init<<<1, 32>>>(prompt, de_cls, w_g, gboost, degra_w, degra_b);

    dim3 tb(32, 8);
    k_trans<<<dim3(NCH / 32, NW / 32, NB * NH), tb>>>(x);

    k_prep<<<3072, 256>>>(fc1w, fc2w);
    k_gate<<<GBLK, 64>>>(w_g);
    k_loss<<<1, 512>>>(out, out_size);

    cudaFuncSetAttribute(k_moe, cudaFuncAttributeMaxDynamicSharedMemorySize, S2_BYTES);
    k_moe<<<NE * 512, 256, S2_BYTES>>>(fc1b, fc2b);

    k_out<<<dim3(NCH / 32, NW / 32, NB * NH), tb>>>(out);
}

// round 4
// speedup vs baseline: 2.0395x; 1.0395x over previous
#include <cuda_runtime.h>
#include <cuda_bf16.h>
#include <math.h>

// ---------------- problem constants ----------------
#define NB   2
#define NCH  128
#define NH   128
#define NW   128
#define NE   6
#define ND   6
#define NHF  512
#define NHW  (NH*NW)        // 16384
#define NTOK (NB*NH*NW)     // 32768
#define NOUT (NTOK*NCH)
#define GBLK 128            // gate blocks (256 tokens each)
#define LCAP (2*NTOK)       // per-expert list capacity

// ---------------- scratch ----------------
__device__ float g_xf[NTOK * NCH];
__device__ float g_res[NTOK * 2 * NCH];
__device__ int   g_list[NE * LCAP];
__device__ float g_gate[NE * LCAP];
__device__ int   g_cnt[NE];
__device__ float g_bias[NB * NE];
__device__ float g_partW[GBLK * NE];
__device__ float g_partC[GBLK * NE];
__device__ unsigned g_done;

// pre-split weights (bf16 hi/lo), B layout [n][k]
__device__ __align__(16) __nv_bfloat16 g_w1t_hi[NE * NHF * NCH];
__device__ __align__(16) __nv_bfloat16 g_w1t_lo[NE * NHF * NCH];
__device__ __align__(16) __nv_bfloat16 g_w2t_hi[NE * NHF * NCH];
__device__ __align__(16) __nv_bfloat16 g_w2t_lo[NE * NHF * NCH];

__device__ __forceinline__ float gelu_exact(float z) {
    return 0.5f * z * (1.0f + erff(z * 0.7071067811865475f));
}
__device__ __forceinline__ void split2(float a0, float a1, unsigned& hi, unsigned& lo) {
    __nv_bfloat16 h0 = __float2bfloat16_rn(a0);
    __nv_bfloat16 h1 = __float2bfloat16_rn(a1);
    __nv_bfloat16 l0 = __float2bfloat16_rn(a0 - __bfloat162float(h0));
    __nv_bfloat16 l1 = __float2bfloat16_rn(a1 - __bfloat162float(h1));
    hi = ((unsigned)__bfloat16_as_ushort(h1) << 16) | __bfloat16_as_ushort(h0);
    lo = ((unsigned)__bfloat16_as_ushort(l1) << 16) | __bfloat16_as_ushort(l0);
}
__device__ __forceinline__ void mma16816(float* c, const unsigned* a, const unsigned* b) {
    asm volatile("mma.sync.aligned.m16n8k16.row.col.f32.bf16.bf16.f32 "
                 "{%0,%1,%2,%3}, {%4,%5,%6,%7}, {%8,%9}, {%0,%1,%2,%3};"
                 : "+f"(c[0]), "+f"(c[1]), "+f"(c[2]), "+f"(c[3])
                 : "r"(a[0]), "r"(a[1]), "r"(a[2]), "r"(a[3]),
                   "r"(b[0]), "r"(b[1]));
}
__device__ __forceinline__ unsigned smem_u32(const void* p) {
    unsigned a;
    asm("{ .reg .u64 t; cvta.to.shared.u64 t, %1; cvt.u32.u64 %0, t; }" : "=r"(a) : "l"(p));
    return a;
}
#define CP16(dst, src) \
    asm volatile("cp.async.cg.shared.global [%0], [%1], 16;" :: "r"(dst), "l"(src))
#define CP_COMMIT() asm volatile("cp.async.commit_group;" ::: "memory")
#define CP_WAIT(n)  asm volatile("cp.async.wait_group %0;" :: "n"(n) : "memory")

// ---------------- kernel 1: init ----------------
__global__ void k_init(const float* __restrict__ prompt,
                       const float* __restrict__ de_cls,
                       const float* __restrict__ w_g,
                       const float* __restrict__ gboost,
                       const float* __restrict__ degra_w,
                       const float* __restrict__ degra_b) {
    int t = threadIdx.x;
    if (t < NB * NE) {
        int b = t / NE, e = t % NE;
        float s1 = 0.f;
        for (int c = 0; c < NCH; c++)
            s1 += prompt[b * NCH + c] * w_g[(NCH + c) * NE + e];
        float s2 = 0.f;
        for (int d = 0; d < ND; d++)
            s2 += de_cls[b * ND + d] * degra_w[d * NE + e];
        g_bias[t] = s1 + gboost[0] * (s2 + degra_b[e]);
    }
    if (t < NE) g_cnt[t] = 0;
    if (t == 31) g_done = 0;
}

// ---------------- kernel 2: transpose x -> xf ----------------
__global__ void k_trans(const float* __restrict__ x) {
    __shared__ float tile[32][33];
    int bh = blockIdx.z;
    int b = bh / NH, h = bh % NH;
    int c0 = blockIdx.x * 32, w0 = blockIdx.y * 32;
    int tx = threadIdx.x, ty = threadIdx.y;
    for (int i = ty; i < 32; i += 8)
        tile[i][tx] = x[(((size_t)b * NCH + c0 + i) * NH + h) * NW + w0 + tx];
    __syncthreads();
    for (int i = ty; i < 32; i += 8)
        g_xf[((size_t)(b * NHW + h * NW + w0 + i)) * NCH + c0 + tx] = tile[tx][i];
}

// ---------------- kernel 3: gating from x (coalesced) + fused loss ----------
__global__ void __launch_bounds__(256)
k_gate(const float* __restrict__ x, const float* __restrict__ w_g,
       float* __restrict__ out, int out_size) {
    __shared__ float wg_s[NCH * NE];
    __shared__ float wsum[8][NE];
    __shared__ int   wcnt[8][NE];
    __shared__ unsigned is_last_s;
    int tid = threadIdx.x;
    for (int i = tid; i < NCH * NE; i += 256) wg_s[i] = w_g[i];
    __syncthreads();

    int n = blockIdx.x * 256 + tid;
    int b = n >> 14;                 // / NHW
    int hw = n & (NHW - 1);
    float acc[NE];
#pragma unroll
    for (int e = 0; e < NE; e++) acc[e] = g_bias[b * NE + e];
    const float* xb = x + (size_t)b * NCH * NHW + hw;
#pragma unroll 4
    for (int c = 0; c < NCH; c++) {
        float xv = xb[(size_t)c * NHW];
#pragma unroll
        for (int e = 0; e < NE; e++) acc[e] += xv * wg_s[c * NE + e];
    }
    int i0 = 0; float v0 = acc[0];
#pragma unroll
    for (int e = 1; e < NE; e++) if (acc[e] > v0) { v0 = acc[e]; i0 = e; }
    int i1 = (i0 == 0) ? 1 : 0; float v1 = acc[i1];
#pragma unroll
    for (int e = 0; e < NE; e++)
        if (e != i0 && acc[e] > v1) { v1 = acc[e]; i1 = e; }
    float g0 = 1.f / (1.f + expf(v1 - v0));
    float g1 = 1.f - g0;

    int p0 = atomicAdd(&g_cnt[i0], 1);
    g_list[i0 * LCAP + p0] = n * 2 + 0;
    g_gate[i0 * LCAP + p0] = g0;
    int p1 = atomicAdd(&g_cnt[i1], 1);
    g_list[i1 * LCAP + p1] = n * 2 + 1;
    g_gate[i1 * LCAP + p1] = g1;

    int warp = tid >> 5, lane = tid & 31;
#pragma unroll
    for (int e = 0; e < NE; e++) {
        float gv = (i0 == e ? g0 : 0.f) + (i1 == e ? g1 : 0.f);
        int   cv = (i0 == e) + (i1 == e);
        for (int off = 16; off; off >>= 1) {
            gv += __shfl_down_sync(0xffffffffu, gv, off);
            cv += __shfl_down_sync(0xffffffffu, cv, off);
        }
        if (lane == 0) { wsum[warp][e] = gv; wcnt[warp][e] = cv; }
    }
    __syncthreads();
    if (tid < NE) {
        float s = 0.f; int c = 0;
#pragma unroll
        for (int w = 0; w < 8; w++) { s += wsum[w][tid]; c += wcnt[w][tid]; }
        g_partW[blockIdx.x * NE + tid] = s;
        g_partC[blockIdx.x * NE + tid] = (float)c;
    }
    // last-block loss reduction (deterministic fixed-order)
    __threadfence();
    __syncthreads();
    if (tid == 0) is_last_s = (atomicAdd(&g_done, 1u) == GBLK - 1);
    __syncthreads();
    if (is_last_s) {
        // warp e (e<6) reduces expert e over 128 blocks
        if (warp < NE) {
            float sW = g_partW[lane * NE + warp] + g_partW[(lane + 32) * NE + warp]
                     + g_partW[(lane + 64) * NE + warp] + g_partW[(lane + 96) * NE + warp];
            float sC = g_partC[lane * NE + warp] + g_partC[(lane + 32) * NE + warp]
                     + g_partC[(lane + 64) * NE + warp] + g_partC[(lane + 96) * NE + warp];
            for (int off = 16; off; off >>= 1) {
                sW += __shfl_down_sync(0xffffffffu, sW, off);
                sC += __shfl_down_sync(0xffffffffu, sC, off);
            }
            if (lane == 0) { wsum[0][warp] = sW; wsum[1][warp] = sC; }
        }
        __syncthreads();
        if (tid == 0 && out_size > NOUT) {
            float mW = 0.f, mC = 0.f;
            for (int e = 0; e < NE; e++) { mW += wsum[0][e]; mC += wsum[1][e]; }
            mW /= NE; mC /= NE;
            float vW = 0.f, vC = 0.f;
            for (int e = 0; e < NE; e++) {
                vW += (wsum[0][e] - mW) * (wsum[0][e] - mW);
                vC += (wsum[1][e] - mC) * (wsum[1][e] - mC);
            }
            vW /= (NE - 1); vC /= (NE - 1);
            out[NOUT] = vW / (mW * mW + 1e-10f) + vC / (mC * mC + 1e-10f);
        }
    }
}

// ---------------- kernel 4b: weight prep ----------------
#define W1ELEM (NE * NHF * NCH)
__global__ void k_prep(const float* __restrict__ fc1w, const float* __restrict__ fc2w) {
    int idx = blockIdx.x * 256 + threadIdx.x;
    if (idx < W1ELEM) {
        int e = idx >> 16, rem = idx & 65535;
        int n = rem >> 7, k = rem & 127;
        float v = fc1w[((size_t)e * NCH + k) * NHF + n];
        __nv_bfloat16 h = __float2bfloat16_rn(v);
        g_w1t_hi[idx] = h;
        g_w1t_lo[idx] = __float2bfloat16_rn(v - __bfloat162float(h));
    } else {
        int j = idx - W1ELEM;
        if (j < W1ELEM) {
            int e = j >> 16, rem = j & 65535;
            int jc = rem >> 13, r2 = rem & 8191;
            int c = r2 >> 6, k = r2 & 63;
            float v = fc2w[((size_t)e * NHF + jc * 64 + k) * NCH + c];
            __nv_bfloat16 h = __float2bfloat16_rn(v);
            g_w2t_hi[j] = h;
            g_w2t_lo[j] = __float2bfloat16_rn(v - __bfloat162float(h));
        }
    }
}

// ---------------- kernel 5: mma.sync MoE with cp.async pipelining ------------
// SMEM map (bytes):
#define S2_XH    0                     // [128][136] bf16 = 34816
#define S2_XL    34816
#define S2_W1    69632                 // 2 buffers x (hi,lo) x [64][136] = 4*17408
#define S2_W2H   139264                // [128][72] = 18432
#define S2_W2L   157696
#define S2_HH    176128
#define S2_HL    194560
#define S2_SLOT  212992
#define S2_GATE  213504
#define S2_BYTES 214016

__global__ void __launch_bounds__(256, 1)
k_moe(const float* __restrict__ fc1b, const float* __restrict__ fc2b) {
    int e    = blockIdx.x >> 9;
    int tile = blockIdx.x & 511;
    int cnt  = g_cnt[e];
    int row0 = tile << 7;
    if (row0 >= cnt) return;

    extern __shared__ char sm[];
    unsigned sb = smem_u32(sm);
    __nv_bfloat16* Xh = (__nv_bfloat16*)(sm + S2_XH);
    __nv_bfloat16* Xl = (__nv_bfloat16*)(sm + S2_XL);
    __nv_bfloat16* Hh = (__nv_bfloat16*)(sm + S2_HH);
    __nv_bfloat16* Hl = (__nv_bfloat16*)(sm + S2_HL);
    __nv_bfloat16* W2h = (__nv_bfloat16*)(sm + S2_W2H);
    __nv_bfloat16* W2l = (__nv_bfloat16*)(sm + S2_W2L);
    int*   slot_s = (int*)(sm + S2_SLOT);
    float* gate_s = (float*)(sm + S2_GATE);

    int tid = threadIdx.x;
    int wid = tid >> 5, lt = tid & 31;
    int qr = lt >> 2, qc = lt & 3;
    int m0 = wid * 16;

    const __nv_bfloat16* w1hg = g_w1t_hi + (size_t)e * NHF * NCH;
    const __nv_bfloat16* w1lg = g_w1t_lo + (size_t)e * NHF * NCH;
    const __nv_bfloat16* w2hg = g_w2t_hi + (size_t)e * NHF * NCH;
    const __nv_bfloat16* w2lg = g_w2t_lo + (size_t)e * NHF * NCH;

    // prefetch W1 chunk 0 into buffer 0
    {
        unsigned d = sb + S2_W1;
#pragma unroll
        for (int it = 0; it < 4; it++) {
            int u = tid + it * 256;              // 0..1023
            int n1 = u >> 4, k16 = u & 15;
            unsigned off = (unsigned)(n1 * 136 + k16 * 8) * 2;
            CP16(d + off,         w1hg + n1 * NCH + k16 * 8);
            CP16(d + 17408 + off, w1lg + n1 * NCH + k16 * 8);
        }
        CP_COMMIT();
    }

    if (tid < 128) {
        int r = row0 + tid;
        if (r < cnt) { slot_s[tid] = g_list[e * LCAP + r]; gate_s[tid] = g_gate[e * LCAP + r]; }
        else         { slot_s[tid] = -1; gate_s[tid] = 0.f; }
    }
    __syncthreads();

    // gather X -> split bf16
#pragma unroll
    for (int it = 0; it < 8; it++) {
        int idx = tid + it * 256;
        int r = idx >> 4, c8 = idx & 15;
        float v[8];
        int s = slot_s[r];
        if (s >= 0) {
            const float4* src = (const float4*)(g_xf + (size_t)(s >> 1) * NCH + c8 * 8);
            float4 a = src[0], b = src[1];
            v[0]=a.x; v[1]=a.y; v[2]=a.z; v[3]=a.w; v[4]=b.x; v[5]=b.y; v[6]=b.z; v[7]=b.w;
        } else {
#pragma unroll
            for (int q = 0; q < 8; q++) v[q] = 0.f;
        }
        uint4 Uh, Ul;
        split2(v[0], v[1], Uh.x, Ul.x);
        split2(v[2], v[3], Uh.y, Ul.y);
        split2(v[4], v[5], Uh.z, Ul.z);
        split2(v[6], v[7], Uh.w, Ul.w);
        *(uint4*)(Xh + r * 136 + c8 * 8) = Uh;
        *(uint4*)(Xl + r * 136 + c8 * 8) = Ul;
    }

    float acc2[16][4];
#pragma unroll
    for (int j = 0; j < 16; j++)
#pragma unroll
        for (int q = 0; q < 4; q++) acc2[j][q] = 0.f;

    for (int jc = 0; jc < 8; jc++) {
        int cur = jc & 1;
        __nv_bfloat16* W1h = (__nv_bfloat16*)(sm + S2_W1 + cur * 34816);
        __nv_bfloat16* W1l = W1h + 8704;     // +17408 bytes

        // issue W2(jc) async (W2 buffer free: post-GEMM2 sync of prev chunk passed)
        {
            unsigned dh = sb + S2_W2H, dl = sb + S2_W2L;
            const __nv_bfloat16* s2h = w2hg + jc * 8192;
            const __nv_bfloat16* s2l = w2lg + jc * 8192;
#pragma unroll
            for (int it = 0; it < 4; it++) {
                int u = tid + it * 256;
                int n2 = u >> 3, k8 = u & 7;
                unsigned off = (unsigned)(n2 * 72 + k8 * 8) * 2;
                CP16(dh + off, s2h + n2 * 64 + k8 * 8);
                CP16(dl + off, s2l + n2 * 64 + k8 * 8);
            }
            CP_COMMIT();
        }
        CP_WAIT(1);              // W1(jc) arrived (W2 may still be in flight)
        __syncthreads();

        // GEMM1: [128 x 64] = X * W1^T, 3-pass split
        float acc1[8][4];
#pragma unroll
        for (int j = 0; j < 8; j++)
#pragma unroll
            for (int q = 0; q < 4; q++) acc1[j][q] = 0.f;

#pragma unroll
        for (int kt = 0; kt < 8; kt++) {
            int row = m0 + qr, col = kt * 16 + qc * 2;
            unsigned ah[4], al[4];
            ah[0] = *(const unsigned*)(Xh + row * 136 + col);
            ah[1] = *(const unsigned*)(Xh + (row + 8) * 136 + col);
            ah[2] = *(const unsigned*)(Xh + row * 136 + col + 8);
            ah[3] = *(const unsigned*)(Xh + (row + 8) * 136 + col + 8);
            al[0] = *(const unsigned*)(Xl + row * 136 + col);
            al[1] = *(const unsigned*)(Xl + (row + 8) * 136 + col);
            al[2] = *(const unsigned*)(Xl + row * 136 + col + 8);
            al[3] = *(const unsigned*)(Xl + (row + 8) * 136 + col + 8);
#pragma unroll
            for (int j = 0; j < 8; j++) {
                int n = j * 8 + qr;
                unsigned bh[2], bl[2];
                bh[0] = *(const unsigned*)(W1h + n * 136 + col);
                bh[1] = *(const unsigned*)(W1h + n * 136 + col + 8);
                bl[0] = *(const unsigned*)(W1l + n * 136 + col);
                bl[1] = *(const unsigned*)(W1l + n * 136 + col + 8);
                mma16816(acc1[j], ah, bh);
                mma16816(acc1[j], ah, bl);
                mma16816(acc1[j], al, bh);
            }
        }

        // bias + gelu -> H
#pragma unroll
        for (int j = 0; j < 8; j++) {
            int n = j * 8 + qc * 2;
            float2 b1 = *(const float2*)(fc1b + e * NHF + jc * 64 + n);
            float h0 = gelu_exact(acc1[j][0] + b1.x);
            float h1 = gelu_exact(acc1[j][1] + b1.y);
            float h2 = gelu_exact(acc1[j][2] + b1.x);
            float h3 = gelu_exact(acc1[j][3] + b1.y);
            unsigned hi, lo;
            split2(h0, h1, hi, lo);
            *(unsigned*)(Hh + (m0 + qr) * 72 + n) = hi;
            *(unsigned*)(Hl + (m0 + qr) * 72 + n) = lo;
            split2(h2, h3, hi, lo);
            *(unsigned*)(Hh + (m0 + qr + 8) * 72 + n) = hi;
            *(unsigned*)(Hl + (m0 + qr + 8) * 72 + n) = lo;
        }
        CP_WAIT(0);              // W2(jc) arrived
        __syncthreads();         // H visible + W2 visible

        // prefetch W1(jc+1) into other buffer during GEMM2
        if (jc < 7) {
            unsigned d = sb + S2_W1 + (1 - cur) * 34816;
            const __nv_bfloat16* s1h = w1hg + (jc + 1) * 64 * NCH;
            const __nv_bfloat16* s1l = w1lg + (jc + 1) * 64 * NCH;
#pragma unroll
            for (int it = 0; it < 4; it++) {
                int u = tid + it * 256;
                int n1 = u >> 4, k16 = u & 15;
                unsigned off = (unsigned)(n1 * 136 + k16 * 8) * 2;
                CP16(d + off,         s1h + n1 * NCH + k16 * 8);
                CP16(d + 17408 + off, s1l + n1 * NCH + k16 * 8);
            }
            CP_COMMIT();
        }

        // GEMM2: [128 x 128] += H * W2^T, 3-pass split
#pragma unroll
        for (int kt = 0; kt < 4; kt++) {
            int row = m0 + qr, col = kt * 16 + qc * 2;
            unsigned ah[4], al[4];
            ah[0] = *(const unsigned*)(Hh + row * 72 + col);
            ah[1] = *(const unsigned*)(Hh + (row + 8) * 72 + col);
            ah[2] = *(const unsigned*)(Hh + row * 72 + col + 8);
            ah[3] = *(const unsigned*)(Hh + (row + 8) * 72 + col + 8);
            al[0] = *(const unsigned*)(Hl + row * 72 + col);
            al[1] = *(const unsigned*)(Hl + (row + 8) * 72 + col);
            al[2] = *(const unsigned*)(Hl + row * 72 + col + 8);
            al[3] = *(const unsigned*)(Hl + (row + 8) * 72 + col + 8);
#pragma unroll
            for (int j = 0; j < 16; j++) {
                int n = j * 8 + qr;
                unsigned bh[2], bl[2];
                bh[0] = *(const unsigned*)(W2h + n * 72 + col);
                bh[1] = *(const unsigned*)(W2h + n * 72 + col + 8);
                bl[0] = *(const unsigned*)(W2l + n * 72 + col);
                bl[1] = *(const unsigned*)(W2l + n * 72 + col + 8);
                mma16816(acc2[j], ah, bh);
                mma16816(acc2[j], ah, bl);
                mma16816(acc2[j], al, bh);
            }
        }
        __syncthreads();         // protect H + W2 for next chunk
    }

    // epilogue: gate * exp(out + b2) -> g_res
    int mA = m0 + qr, mB = m0 + qr + 8;
    int sA = slot_s[mA], sB = slot_s[mB];
    float gA = gate_s[mA], gB = gate_s[mB];
#pragma unroll
    for (int j = 0; j < 16; j++) {
        int c = j * 8 + qc * 2;
        float2 b2 = *(const float2*)(fc2b + e * NCH + c);
        if (sA >= 0) {
            float2 o;
            o.x = gA * expf(acc2[j][0] + b2.x);
            o.y = gA * expf(acc2[j][1] + b2.y);
            *(float2*)(g_res + (size_t)sA * NCH + c) = o;
        }
        if (sB >= 0) {
            float2 o;
            o.x = gB * expf(acc2[j][2] + b2.x);
            o.y = gB * expf(acc2[j][3] + b2.y);
            *(float2*)(g_res + (size_t)sB * NCH + c) = o;
        }
    }
}

// ---------------- kernel 6: combine + log + transpose back ----------------
__global__ void k_out(float* __restrict__ out) {
    __shared__ float tile[32][33];
    int bh = blockIdx.z;
    int b = bh / NH, h = bh % NH;
    int c0 = blockIdx.x * 32, w0 = blockIdx.y * 32;
    int tx = threadIdx.x, ty = threadIdx.y;
    for (int i = ty; i < 32; i += 8) {
        size_t base = (size_t)(b * NHW + h * NW + w0 + i) * 2 * NCH;
        float v = g_res[base + c0 + tx] + g_res[base + NCH + c0 + tx];
        if (v == 0.f) v = 2.2204460492503131e-16f;
        tile[i][tx] = logf(v);
    }
    __syncthreads();
    for (int i = ty; i < 32; i += 8)
        out[(((size_t)b * NCH + c0 + i) * NH + h) * NW + w0 + tx] = tile[tx][i];
}

// ---------------- launch ----------------
extern "C" void kernel_launch(void* const* d_in, const int* in_sizes, int n_in,
                              void* d_out, int out_size) {
    (void)in_sizes; (void)n_in;
    const float* x       = (const float*)d_in[0];
    const float* prompt  = (const float*)d_in[1];
    const float* de_cls  = (const float*)d_in[2];
    const float* w_g     = (const float*)d_in[3];
    const float* gboost  = (const float*)d_in[4];
    const float* degra_w = (const float*)d_in[5];
    const float* degra_b = (const float*)d_in[6];
    const float* fc1w    = (const float*)d_in[7];
    const float* fc1b    = (const float*)d_in[8];
    const float* fc2w    = (const float*)d_in[9];
    const float* fc2b    = (const float*)d_in[10];
    float* out = (float*)d_out;

    k_init<<<1, 32>>>(prompt, de_cls, w_g, gboost, degra_w, degra_b);
    k_gate<<<GBLK, 256>>>(x, w_g, out, out_size);

    dim3 tb(32, 8);
    k_trans<<<dim3(NCH / 32, NW / 32, NB * NH), tb>>>(x);
    k_prep<<<3072, 256>>>(fc1w, fc2w);

    cudaFuncSetAttribute(k_moe, cudaFuncAttributeMaxDynamicSharedMemorySize, S2_BYTES);
    k_moe<<<NE * 512, 256, S2_BYTES>>>(fc1b, fc2b);

    k_out<<<dim3(NCH / 32, NW / 32, NB * NH), tb>>>(out);
}

// round 5
// speedup vs baseline: 2.5203x; 1.2358x over previous
#include <cuda_runtime.h>
#include <cuda_bf16.h>
#include <cuda_fp16.h>
#include <math.h>

// ---------------- problem constants ----------------
#define NB   2
#define NCH  128
#define NH   128
#define NW   128
#define NE   6
#define ND   6
#define NHF  512
#define NHW  (NH*NW)        // 16384
#define NTOK (NB*NH*NW)     // 32768
#define NOUT (NTOK*NCH)
#define GBLK 128            // gate blocks (256 tokens each)
#define LCAP (2*NTOK)       // per-expert list capacity

// ---------------- scratch ----------------
__device__ float g_xf[NTOK * NCH];
__device__ float g_res[NTOK * 2 * NCH];
__device__ int   g_list[NE * LCAP];
__device__ float g_gate[NE * LCAP];
__device__ int   g_cnt[NE];
__device__ float g_bias[NB * NE];
__device__ float g_partW[GBLK * NE];
__device__ float g_partC[GBLK * NE];
__device__ unsigned g_done;

// fp16 weights, B layout [n][k]
__device__ __align__(16) __half g_w1t[NE * NHF * NCH];
__device__ __align__(16) __half g_w2t[NE * NHF * NCH];

__device__ __forceinline__ float gelu_exact(float z) {
    return 0.5f * z * (1.0f + erff(z * 0.7071067811865475f));
}
__device__ __forceinline__ void split2h(float a0, float a1, unsigned& hi, unsigned& lo) {
    __half h0 = __float2half_rn(a0);
    __half h1 = __float2half_rn(a1);
    __half l0 = __float2half_rn(a0 - __half2float(h0));
    __half l1 = __float2half_rn(a1 - __half2float(h1));
    hi = ((unsigned)__half_as_ushort(h1) << 16) | __half_as_ushort(h0);
    lo = ((unsigned)__half_as_ushort(l1) << 16) | __half_as_ushort(l0);
}
__device__ __forceinline__ void mma16816h(float* c, const unsigned* a, const unsigned* b) {
    asm volatile("mma.sync.aligned.m16n8k16.row.col.f32.f16.f16.f32 "
                 "{%0,%1,%2,%3}, {%4,%5,%6,%7}, {%8,%9}, {%0,%1,%2,%3};"
                 : "+f"(c[0]), "+f"(c[1]), "+f"(c[2]), "+f"(c[3])
                 : "r"(a[0]), "r"(a[1]), "r"(a[2]), "r"(a[3]),
                   "r"(b[0]), "r"(b[1]));
}
__device__ __forceinline__ unsigned smem_u32(const void* p) {
    unsigned a;
    asm("{ .reg .u64 t; cvta.to.shared.u64 t, %1; cvt.u32.u64 %0, t; }" : "=r"(a) : "l"(p));
    return a;
}
#define CP16(dst, src) \
    asm volatile("cp.async.cg.shared.global [%0], [%1], 16;" :: "r"(dst), "l"(src))
#define CP_COMMIT() asm volatile("cp.async.commit_group;" ::: "memory")
#define CP_WAIT(n)  asm volatile("cp.async.wait_group %0;" :: "n"(n) : "memory")

// ---------------- kernel 1: init ----------------
__global__ void k_init(const float* __restrict__ prompt,
                       const float* __restrict__ de_cls,
                       const float* __restrict__ w_g,
                       const float* __restrict__ gboost,
                       const float* __restrict__ degra_w,
                       const float* __restrict__ degra_b) {
    int t = threadIdx.x;
    if (t < NB * NE) {
        int b = t / NE, e = t % NE;
        float s1 = 0.f;
        for (int c = 0; c < NCH; c++)
            s1 += prompt[b * NCH + c] * w_g[(NCH + c) * NE + e];
        float s2 = 0.f;
        for (int d = 0; d < ND; d++)
            s2 += de_cls[b * ND + d] * degra_w[d * NE + e];
        g_bias[t] = s1 + gboost[0] * (s2 + degra_b[e]);
    }
    if (t < NE) g_cnt[t] = 0;
    if (t == 31) g_done = 0;
}

// ---------------- kernel 2: transpose x -> xf ----------------
__global__ void k_trans(const float* __restrict__ x) {
    __shared__ float tile[32][33];
    int bh = blockIdx.z;
    int b = bh / NH, h = bh % NH;
    int c0 = blockIdx.x * 32, w0 = blockIdx.y * 32;
    int tx = threadIdx.x, ty = threadIdx.y;
    for (int i = ty; i < 32; i += 8)
        tile[i][tx] = x[(((size_t)b * NCH + c0 + i) * NH + h) * NW + w0 + tx];
    __syncthreads();
    for (int i = ty; i < 32; i += 8)
        g_xf[((size_t)(b * NHW + h * NW + w0 + i)) * NCH + c0 + tx] = tile[tx][i];
}

// ---------------- kernel 3: gating (coalesced from x) + fused loss ----------
__global__ void __launch_bounds__(256)
k_gate(const float* __restrict__ x, const float* __restrict__ w_g,
       float* __restrict__ out, int out_size) {
    __shared__ float wg_s[NCH * NE];
    __shared__ float wsum[8][NE];
    __shared__ int   wcnt[8][NE];
    __shared__ unsigned is_last_s;
    int tid = threadIdx.x;
    for (int i = tid; i < NCH * NE; i += 256) wg_s[i] = w_g[i];
    __syncthreads();

    int n = blockIdx.x * 256 + tid;
    int b = n >> 14;
    int hw = n & (NHW - 1);
    float acc[NE];
#pragma unroll
    for (int e = 0; e < NE; e++) acc[e] = g_bias[b * NE + e];
    const float* xb = x + (size_t)b * NCH * NHW + hw;
#pragma unroll 4
    for (int c = 0; c < NCH; c++) {
        float xv = xb[(size_t)c * NHW];
#pragma unroll
        for (int e = 0; e < NE; e++) acc[e] += xv * wg_s[c * NE + e];
    }
    int i0 = 0; float v0 = acc[0];
#pragma unroll
    for (int e = 1; e < NE; e++) if (acc[e] > v0) { v0 = acc[e]; i0 = e; }
    int i1 = (i0 == 0) ? 1 : 0; float v1 = acc[i1];
#pragma unroll
    for (int e = 0; e < NE; e++)
        if (e != i0 && acc[e] > v1) { v1 = acc[e]; i1 = e; }
    float g0 = 1.f / (1.f + expf(v1 - v0));
    float g1 = 1.f - g0;

    int p0 = atomicAdd(&g_cnt[i0], 1);
    g_list[i0 * LCAP + p0] = n * 2 + 0;
    g_gate[i0 * LCAP + p0] = g0;
    int p1 = atomicAdd(&g_cnt[i1], 1);
    g_list[i1 * LCAP + p1] = n * 2 + 1;
    g_gate[i1 * LCAP + p1] = g1;

    int warp = tid >> 5, lane = tid & 31;
#pragma unroll
    for (int e = 0; e < NE; e++) {
        float gv = (i0 == e ? g0 : 0.f) + (i1 == e ? g1 : 0.f);
        int   cv = (i0 == e) + (i1 == e);
        for (int off = 16; off; off >>= 1) {
            gv += __shfl_down_sync(0xffffffffu, gv, off);
            cv += __shfl_down_sync(0xffffffffu, cv, off);
        }
        if (lane == 0) { wsum[warp][e] = gv; wcnt[warp][e] = cv; }
    }
    __syncthreads();
    if (tid < NE) {
        float s = 0.f; int c = 0;
#pragma unroll
        for (int w = 0; w < 8; w++) { s += wsum[w][tid]; c += wcnt[w][tid]; }
        g_partW[blockIdx.x * NE + tid] = s;
        g_partC[blockIdx.x * NE + tid] = (float)c;
    }
    __threadfence();
    __syncthreads();
    if (tid == 0) is_last_s = (atomicAdd(&g_done, 1u) == GBLK - 1);
    __syncthreads();
    if (is_last_s) {
        if (warp < NE) {
            float sW = g_partW[lane * NE + warp] + g_partW[(lane + 32) * NE + warp]
                     + g_partW[(lane + 64) * NE + warp] + g_partW[(lane + 96) * NE + warp];
            float sC = g_partC[lane * NE + warp] + g_partC[(lane + 32) * NE + warp]
                     + g_partC[(lane + 64) * NE + warp] + g_partC[(lane + 96) * NE + warp];
            for (int off = 16; off; off >>= 1) {
                sW += __shfl_down_sync(0xffffffffu, sW, off);
                sC += __shfl_down_sync(0xffffffffu, sC, off);
            }
            if (lane == 0) { wsum[0][warp] = sW; wsum[1][warp] = sC; }
        }
        __syncthreads();
        if (tid == 0 && out_size > NOUT) {
            float mW = 0.f, mC = 0.f;
            for (int e = 0; e < NE; e++) { mW += wsum[0][e]; mC += wsum[1][e]; }
            mW /= NE; mC /= NE;
            float vW = 0.f, vC = 0.f;
            for (int e = 0; e < NE; e++) {
                vW += (wsum[0][e] - mW) * (wsum[0][e] - mW);
                vC += (wsum[1][e] - mC) * (wsum[1][e] - mC);
            }
            vW /= (NE - 1); vC /= (NE - 1);
            out[NOUT] = vW / (mW * mW + 1e-10f) + vC / (mC * mC + 1e-10f);
        }
    }
}

// ---------------- kernel 4b: weight prep (fp16, transpose to [n][k]) --------
#define W1ELEM (NE * NHF * NCH)
__global__ void k_prep(const float* __restrict__ fc1w, const float* __restrict__ fc2w) {
    int idx = blockIdx.x * 256 + threadIdx.x;
    if (idx < W1ELEM) {
        int e = idx >> 16, rem = idx & 65535;
        int n = rem >> 7, k = rem & 127;
        g_w1t[idx] = __float2half_rn(fc1w[((size_t)e * NCH + k) * NHF + n]);
    } else {
        int j = idx - W1ELEM;
        if (j < W1ELEM) {
            int e = j >> 16, rem = j & 65535;
            int jc = rem >> 13, r2 = rem & 8191;
            int c = r2 >> 6, k = r2 & 63;
            g_w2t[j] = __float2half_rn(fc2w[((size_t)e * NHF + jc * 64 + k) * NCH + c]);
        }
    }
}

// ---------------- kernel 5: fp16 2-pass mma MoE ------------------------------
// SMEM map (bytes):
#define S2_XH    0                     // [128][136] half = 34816
#define S2_XL    34816
#define S2_W1    69632                 // 2 buffers x [64][136] half = 2*17408
#define S2_W2    104448                // [128][72] half = 18432
#define S2_HH    122880
#define S2_HL    141312
#define S2_SLOT  159744
#define S2_GATE  160256
#define S2_BYTES 160768

__global__ void __launch_bounds__(256, 1)
k_moe(const float* __restrict__ fc1b, const float* __restrict__ fc2b) {
    int e    = blockIdx.x >> 9;
    int tile = blockIdx.x & 511;
    int cnt  = g_cnt[e];
    int row0 = tile << 7;
    if (row0 >= cnt) return;

    extern __shared__ char sm[];
    unsigned sb = smem_u32(sm);
    __half* Xh = (__half*)(sm + S2_XH);
    __half* Xl = (__half*)(sm + S2_XL);
    __half* W2 = (__half*)(sm + S2_W2);
    __half* Hh = (__half*)(sm + S2_HH);
    __half* Hl = (__half*)(sm + S2_HL);
    int*   slot_s = (int*)(sm + S2_SLOT);
    float* gate_s = (float*)(sm + S2_GATE);

    int tid = threadIdx.x;
    int wid = tid >> 5, lt = tid & 31;
    int qr = lt >> 2, qc = lt & 3;
    int m0 = wid * 16;

    const __half* w1g = g_w1t + (size_t)e * NHF * NCH;
    const __half* w2g = g_w2t + (size_t)e * NHF * NCH;

    // prefetch W1 chunk 0 into buffer 0
    {
        unsigned d = sb + S2_W1;
#pragma unroll
        for (int it = 0; it < 4; it++) {
            int u = tid + it * 256;              // 0..1023
            int n1 = u >> 4, k16 = u & 15;
            CP16(d + (unsigned)(n1 * 136 + k16 * 8) * 2, w1g + n1 * NCH + k16 * 8);
        }
        CP_COMMIT();
    }

    if (tid < 128) {
        int r = row0 + tid;
        if (r < cnt) { slot_s[tid] = g_list[e * LCAP + r]; gate_s[tid] = g_gate[e * LCAP + r]; }
        else         { slot_s[tid] = -1; gate_s[tid] = 0.f; }
    }
    __syncthreads();

    // gather X -> split fp16 hi/lo
#pragma unroll
    for (int it = 0; it < 8; it++) {
        int idx = tid + it * 256;
        int r = idx >> 4, c8 = idx & 15;
        float v[8];
        int s = slot_s[r];
        if (s >= 0) {
            const float4* src = (const float4*)(g_xf + (size_t)(s >> 1) * NCH + c8 * 8);
            float4 a = src[0], b = src[1];
            v[0]=a.x; v[1]=a.y; v[2]=a.z; v[3]=a.w; v[4]=b.x; v[5]=b.y; v[6]=b.z; v[7]=b.w;
        } else {
#pragma unroll
            for (int q = 0; q < 8; q++) v[q] = 0.f;
        }
        uint4 Uh, Ul;
        split2h(v[0], v[1], Uh.x, Ul.x);
        split2h(v[2], v[3], Uh.y, Ul.y);
        split2h(v[4], v[5], Uh.z, Ul.z);
        split2h(v[6], v[7], Uh.w, Ul.w);
        *(uint4*)(Xh + r * 136 + c8 * 8) = Uh;
        *(uint4*)(Xl + r * 136 + c8 * 8) = Ul;
    }

    float acc2[16][4];
#pragma unroll
    for (int j = 0; j < 16; j++)
#pragma unroll
        for (int q = 0; q < 4; q++) acc2[j][q] = 0.f;

    for (int jc = 0; jc < 8; jc++) {
        int cur = jc & 1;
        __half* W1 = (__half*)(sm + S2_W1 + cur * 17408);

        // issue W2(jc) async
        {
            unsigned d2 = sb + S2_W2;
            const __half* s2 = w2g + jc * 8192;
#pragma unroll
            for (int it = 0; it < 4; it++) {
                int u = tid + it * 256;
                int n2 = u >> 3, k8 = u & 7;
                CP16(d2 + (unsigned)(n2 * 72 + k8 * 8) * 2, s2 + n2 * 64 + k8 * 8);
            }
            CP_COMMIT();
        }
        CP_WAIT(1);              // W1(jc) arrived
        __syncthreads();

        // GEMM1: [128 x 64] = X * W1^T, 2-pass (X split, W1 single fp16)
        float acc1[8][4];
#pragma unroll
        for (int j = 0; j < 8; j++)
#pragma unroll
            for (int q = 0; q < 4; q++) acc1[j][q] = 0.f;

#pragma unroll
        for (int kt = 0; kt < 8; kt++) {
            int row = m0 + qr, col = kt * 16 + qc * 2;
            unsigned ah[4], al[4];
            ah[0] = *(const unsigned*)(Xh + row * 136 + col);
            ah[1] = *(const unsigned*)(Xh + (row + 8) * 136 + col);
            ah[2] = *(const unsigned*)(Xh + row * 136 + col + 8);
            ah[3] = *(const unsigned*)(Xh + (row + 8) * 136 + col + 8);
            al[0] = *(const unsigned*)(Xl + row * 136 + col);
            al[1] = *(const unsigned*)(Xl + (row + 8) * 136 + col);
            al[2] = *(const unsigned*)(Xl + row * 136 + col + 8);
            al[3] = *(const unsigned*)(Xl + (row + 8) * 136 + col + 8);
#pragma unroll
            for (int j = 0; j < 8; j++) {
                int n = j * 8 + qr;
                unsigned bh[2];
                bh[0] = *(const unsigned*)(W1 + n * 136 + col);
                bh[1] = *(const unsigned*)(W1 + n * 136 + col + 8);
                mma16816h(acc1[j], ah, bh);
                mma16816h(acc1[j], al, bh);
            }
        }

        // bias + gelu -> H (split fp16)
#pragma unroll
        for (int j = 0; j < 8; j++) {
            int n = j * 8 + qc * 2;
            float2 b1 = *(const float2*)(fc1b + e * NHF + jc * 64 + n);
            float h0 = gelu_exact(acc1[j][0] + b1.x);
            float h1 = gelu_exact(acc1[j][1] + b1.y);
            float h2 = gelu_exact(acc1[j][2] + b1.x);
            float h3 = gelu_exact(acc1[j][3] + b1.y);
            unsigned hi, lo;
            split2h(h0, h1, hi, lo);
            *(unsigned*)(Hh + (m0 + qr) * 72 + n) = hi;
            *(unsigned*)(Hl + (m0 + qr) * 72 + n) = lo;
            split2h(h2, h3, hi, lo);
            *(unsigned*)(Hh + (m0 + qr + 8) * 72 + n) = hi;
            *(unsigned*)(Hl + (m0 + qr + 8) * 72 + n) = lo;
        }
        CP_WAIT(0);              // W2(jc) arrived
        __syncthreads();

        // prefetch W1(jc+1) during GEMM2
        if (jc < 7) {
            unsigned d = sb + S2_W1 + (1 - cur) * 17408;
            const __half* s1 = w1g + (jc + 1) * 64 * NCH;
#pragma unroll
            for (int it = 0; it < 4; it++) {
                int u = tid + it * 256;
                int n1 = u >> 4, k16 = u & 15;
                CP16(d + (unsigned)(n1 * 136 + k16 * 8) * 2, s1 + n1 * NCH + k16 * 8);
            }
            CP_COMMIT();
        }

        // GEMM2: [128 x 128] += H * W2^T, 2-pass
#pragma unroll
        for (int kt = 0; kt < 4; kt++) {
            int row = m0 + qr, col = kt * 16 + qc * 2;
            unsigned ah[4], al[4];
            ah[0] = *(const unsigned*)(Hh + row * 72 + col);
            ah[1] = *(const unsigned*)(Hh + (row + 8) * 72 + col);
            ah[2] = *(const unsigned*)(Hh + row * 72 + col + 8);
            ah[3] = *(const unsigned*)(Hh + (row + 8) * 72 + col + 8);
            al[0] = *(const unsigned*)(Hl + row * 72 + col);
            al[1] = *(const unsigned*)(Hl + (row + 8) * 72 + col);
            al[2] = *(const unsigned*)(Hl + row * 72 + col + 8);
            al[3] = *(const unsigned*)(Hl + (row + 8) * 72 + col + 8);
#pragma unroll
            for (int j = 0; j < 16; j++) {
                int n = j * 8 + qr;
                unsigned bh[2];
                bh[0] = *(const unsigned*)(W2 + n * 72 + col);
                bh[1] = *(const unsigned*)(W2 + n * 72 + col + 8);
                mma16816h(acc2[j], ah, bh);
                mma16816h(acc2[j], al, bh);
            }
        }
        __syncthreads();         // protect H + W2 for next chunk
    }

    // epilogue: gate * exp(out + b2) -> g_res
    int mA = m0 + qr, mB = m0 + qr + 8;
    int sA = slot_s[mA], sB = slot_s[mB];
    float gA = gate_s[mA], gB = gate_s[mB];
#pragma unroll
    for (int j = 0; j < 16; j++) {
        int c = j * 8 + qc * 2;
        float2 b2 = *(const float2*)(fc2b + e * NCH + c);
        if (sA >= 0) {
            float2 o;
            o.x = gA * expf(acc2[j][0] + b2.x);
            o.y = gA * expf(acc2[j][1] + b2.y);
            *(float2*)(g_res + (size_t)sA * NCH + c) = o;
        }
        if (sB >= 0) {
            float2 o;
            o.x = gB * expf(acc2[j][2] + b2.x);
            o.y = gB * expf(acc2[j][3] + b2.y);
            *(float2*)(g_res + (size_t)sB * NCH + c) = o;
        }
    }
}

// ---------------- kernel 6: combine + log + transpose back ----------------
__global__ void k_out(float* __restrict__ out) {
    __shared__ float tile[32][33];
    int bh = blockIdx.z;
    int b = bh / NH, h = bh % NH;
    int c0 = blockIdx.x * 32, w0 = blockIdx.y * 32;
    int tx = threadIdx.x, ty = threadIdx.y;
    for (int i = ty; i < 32; i += 8) {
        size_t base = (size_t)(b * NHW + h * NW + w0 + i) * 2 * NCH;
        float v = g_res[base + c0 + tx] + g_res[base + NCH + c0 + tx];
        if (v == 0.f) v = 2.2204460492503131e-16f;
        tile[i][tx] = logf(v);
    }
    __syncthreads();
    for (int i = ty; i < 32; i += 8)
        out[(((size_t)b * NCH + c0 + i) * NH + h) * NW + w0 + tx] = tile[tx][i];
}

// ---------------- launch ----------------
extern "C" void kernel_launch(void* const* d_in, const int* in_sizes, int n_in,
                              void* d_out, int out_size) {
    (void)in_sizes; (void)n_in;
    const float* x       = (const float*)d_in[0];
    const float* prompt  = (const float*)d_in[1];
    const float* de_cls  = (const float*)d_in[2];
    const float* w_g     = (const float*)d_in[3];
    const float* gboost  = (const float*)d_in[4];
    const float* degra_w = (const float*)d_in[5];
    const float* degra_b = (const float*)d_in[6];
    const float* fc1w    = (const float*)d_in[7];
    const float* fc1b    = (const float*)d_in[8];
    const float* fc2w    = (const float*)d_in[9];
    const float* fc2b    = (const float*)d_in[10];
    float* out = (float*)d_out;

    k_init<<<1, 32>>>(prompt, de_cls, w_g, gboost, degra_w, degra_b);
    k_gate<<<GBLK, 256>>>(x, w_g, out, out_size);

    dim3 tb(32, 8);
    k_trans<<<dim3(NCH / 32, NW / 32, NB * NH), tb>>>(x);
    k_prep<<<3072, 256>>>(fc1w, fc2w);

    cudaFuncSetAttribute(k_moe, cudaFuncAttributeMaxDynamicSharedMemorySize, S2_BYTES);
    k_moe<<<NE * 512, 256, S2_BYTES>>>(fc1b, fc2b);

    k_out<<<dim3(NCH / 32, NW / 32, NB * NH), tb>>>(out);
}

// round 6
// speedup vs baseline: 3.0641x; 1.2158x over previous
#include <cuda_runtime.h>
#include <cuda_bf16.h>
#include <cuda_fp16.h>
#include <math.h>

// ---------------- problem constants ----------------
#define NB   2
#define NCH  128
#define NH   128
#define NW   128
#define NE   6
#define ND   6
#define NHF  512
#define NHW  (NH*NW)        // 16384
#define NTOK (NB*NH*NW)     // 32768
#define NOUT (NTOK*NCH)
#define GBLK 128            // gate blocks (256 tokens each)
#define LCAP (2*NTOK)       // per-expert list capacity

// ---------------- scratch ----------------
__device__ float g_xf[NTOK * NCH];
__device__ float g_res[NTOK * 2 * NCH];
__device__ int   g_list[NE * LCAP];
__device__ float g_gate[NE * LCAP];
__device__ int   g_cnt[NE];
__device__ float g_bias[NB * NE];
__device__ float g_partW[GBLK * NE];
__device__ float g_partC[GBLK * NE];
__device__ unsigned g_done;

// fp16 weights, B layout [n][k]
__device__ __align__(16) __half g_w1t[NE * NHF * NCH];
__device__ __align__(16) __half g_w2t[NE * NHF * NCH];

__device__ __forceinline__ float gelu_exact(float z) {
    return 0.5f * z * (1.0f + erff(z * 0.7071067811865475f));
}
__device__ __forceinline__ unsigned pack2h(float a0, float a1) {
    __half2 h = __floats2half2_rn(a0, a1);
    return *(unsigned*)&h;
}
__device__ __forceinline__ void mma16816h(float* c, const unsigned* a, const unsigned* b) {
    asm volatile("mma.sync.aligned.m16n8k16.row.col.f32.f16.f16.f32 "
                 "{%0,%1,%2,%3}, {%4,%5,%6,%7}, {%8,%9}, {%0,%1,%2,%3};"
                 : "+f"(c[0]), "+f"(c[1]), "+f"(c[2]), "+f"(c[3])
                 : "r"(a[0]), "r"(a[1]), "r"(a[2]), "r"(a[3]),
                   "r"(b[0]), "r"(b[1]));
}
__device__ __forceinline__ unsigned smem_u32(const void* p) {
    unsigned a;
    asm("{ .reg .u64 t; cvta.to.shared.u64 t, %1; cvt.u32.u64 %0, t; }" : "=r"(a) : "l"(p));
    return a;
}
#define CP16(dst, src) \
    asm volatile("cp.async.cg.shared.global [%0], [%1], 16;" :: "r"(dst), "l"(src))
#define CP_COMMIT() asm volatile("cp.async.commit_group;" ::: "memory")
#define CP_WAIT(n)  asm volatile("cp.async.wait_group %0;" :: "n"(n) : "memory")

// ---------------- kernel 1: init ----------------
__global__ void k_init(const float* __restrict__ prompt,
                       const float* __restrict__ de_cls,
                       const float* __restrict__ w_g,
                       const float* __restrict__ gboost,
                       const float* __restrict__ degra_w,
                       const float* __restrict__ degra_b) {
    int t = threadIdx.x;
    if (t < NB * NE) {
        int b = t / NE, e = t % NE;
        float s1 = 0.f;
        for (int c = 0; c < NCH; c++)
            s1 += prompt[b * NCH + c] * w_g[(NCH + c) * NE + e];
        float s2 = 0.f;
        for (int d = 0; d < ND; d++)
            s2 += de_cls[b * ND + d] * degra_w[d * NE + e];
        g_bias[t] = s1 + gboost[0] * (s2 + degra_b[e]);
    }
    if (t < NE) g_cnt[t] = 0;
    if (t == 31) g_done = 0;
}

// ---------------- kernel 2: transpose x -> xf ----------------
__global__ void k_trans(const float* __restrict__ x) {
    __shared__ float tile[32][33];
    int bh = blockIdx.z;
    int b = bh / NH, h = bh % NH;
    int c0 = blockIdx.x * 32, w0 = blockIdx.y * 32;
    int tx = threadIdx.x, ty = threadIdx.y;
    for (int i = ty; i < 32; i += 8)
        tile[i][tx] = x[(((size_t)b * NCH + c0 + i) * NH + h) * NW + w0 + tx];
    __syncthreads();
    for (int i = ty; i < 32; i += 8)
        g_xf[((size_t)(b * NHW + h * NW + w0 + i)) * NCH + c0 + tx] = tile[tx][i];
}

// ---------------- kernel 3: gating (coalesced from x) + fused loss ----------
__global__ void __launch_bounds__(256)
k_gate(const float* __restrict__ x, const float* __restrict__ w_g,
       float* __restrict__ out, int out_size) {
    __shared__ float wg_s[NCH * NE];
    __shared__ float wsum[8][NE];
    __shared__ int   wcnt[8][NE];
    __shared__ unsigned is_last_s;
    int tid = threadIdx.x;
    for (int i = tid; i < NCH * NE; i += 256) wg_s[i] = w_g[i];
    __syncthreads();

    int n = blockIdx.x * 256 + tid;
    int b = n >> 14;
    int hw = n & (NHW - 1);
    float acc[NE];
#pragma unroll
    for (int e = 0; e < NE; e++) acc[e] = g_bias[b * NE + e];
    const float* xb = x + (size_t)b * NCH * NHW + hw;
#pragma unroll 4
    for (int c = 0; c < NCH; c++) {
        float xv = xb[(size_t)c * NHW];
#pragma unroll
        for (int e = 0; e < NE; e++) acc[e] += xv * wg_s[c * NE + e];
    }
    int i0 = 0; float v0 = acc[0];
#pragma unroll
    for (int e = 1; e < NE; e++) if (acc[e] > v0) { v0 = acc[e]; i0 = e; }
    int i1 = (i0 == 0) ? 1 : 0; float v1 = acc[i1];
#pragma unroll
    for (int e = 0; e < NE; e++)
        if (e != i0 && acc[e] > v1) { v1 = acc[e]; i1 = e; }
    float g0 = 1.f / (1.f + expf(v1 - v0));
    float g1 = 1.f - g0;

    int p0 = atomicAdd(&g_cnt[i0], 1);
    g_list[i0 * LCAP + p0] = n * 2 + 0;
    g_gate[i0 * LCAP + p0] = g0;
    int p1 = atomicAdd(&g_cnt[i1], 1);
    g_list[i1 * LCAP + p1] = n * 2 + 1;
    g_gate[i1 * LCAP + p1] = g1;

    int warp = tid >> 5, lane = tid & 31;
#pragma unroll
    for (int e = 0; e < NE; e++) {
        float gv = (i0 == e ? g0 : 0.f) + (i1 == e ? g1 : 0.f);
        int   cv = (i0 == e) + (i1 == e);
        for (int off = 16; off; off >>= 1) {
            gv += __shfl_down_sync(0xffffffffu, gv, off);
            cv += __shfl_down_sync(0xffffffffu, cv, off);
        }
        if (lane == 0) { wsum[warp][e] = gv; wcnt[warp][e] = cv; }
    }
    __syncthreads();
    if (tid < NE) {
        float s = 0.f; int c = 0;
#pragma unroll
        for (int w = 0; w < 8; w++) { s += wsum[w][tid]; c += wcnt[w][tid]; }
        g_partW[blockIdx.x * NE + tid] = s;
        g_partC[blockIdx.x * NE + tid] = (float)c;
    }
    __threadfence();
    __syncthreads();
    if (tid == 0) is_last_s = (atomicAdd(&g_done, 1u) == GBLK - 1);
    __syncthreads();
    if (is_last_s) {
        if (warp < NE) {
            float sW = g_partW[lane * NE + warp] + g_partW[(lane + 32) * NE + warp]
                     + g_partW[(lane + 64) * NE + warp] + g_partW[(lane + 96) * NE + warp];
            float sC = g_partC[lane * NE + warp] + g_partC[(lane + 32) * NE + warp]
                     + g_partC[(lane + 64) * NE + warp] + g_partC[(lane + 96) * NE + warp];
            for (int off = 16; off; off >>= 1) {
                sW += __shfl_down_sync(0xffffffffu, sW, off);
                sC += __shfl_down_sync(0xffffffffu, sC, off);
            }
            if (lane == 0) { wsum[0][warp] = sW; wsum[1][warp] = sC; }
        }
        __syncthreads();
        if (tid == 0 && out_size > NOUT) {
            float mW = 0.f, mC = 0.f;
            for (int e = 0; e < NE; e++) { mW += wsum[0][e]; mC += wsum[1][e]; }
            mW /= NE; mC /= NE;
            float vW = 0.f, vC = 0.f;
            for (int e = 0; e < NE; e++) {
                vW += (wsum[0][e] - mW) * (wsum[0][e] - mW);
                vC += (wsum[1][e] - mC) * (wsum[1][e] - mC);
            }
            vW /= (NE - 1); vC /= (NE - 1);
            out[NOUT] = vW / (mW * mW + 1e-10f) + vC / (mC * mC + 1e-10f);
        }
    }
}

// ---------------- kernel 4b: weight prep (fp16, transpose to [n][k]) --------
#define W1ELEM (NE * NHF * NCH)
__global__ void k_prep(const float* __restrict__ fc1w, const float* __restrict__ fc2w) {
    int idx = blockIdx.x * 256 + threadIdx.x;
    if (idx < W1ELEM) {
        int e = idx >> 16, rem = idx & 65535;
        int n = rem >> 7, k = rem & 127;
        g_w1t[idx] = __float2half_rn(fc1w[((size_t)e * NCH + k) * NHF + n]);
    } else {
        int j = idx - W1ELEM;
        if (j < W1ELEM) {
            int e = j >> 16, rem = j & 65535;
            int jc = rem >> 13, r2 = rem & 8191;
            int c = r2 >> 6, k = r2 & 63;
            g_w2t[j] = __float2half_rn(fc2w[((size_t)e * NHF + jc * 64 + k) * NCH + c]);
        }
    }
}

// ---------------- kernel 5: single-pass fp16 mma MoE -------------------------
// SMEM map (bytes):
#define S2_X     0                     // [128][136] half = 34816
#define S2_W1    34816                 // 2 buffers x [64][136] half = 2*17408
#define S2_W2    69632                 // [128][72] half = 18432
#define S2_H     88064                 // [128][72] half = 18432
#define S2_SLOT  106496
#define S2_GATE  107008
#define S2_BYTES 107520

__global__ void __launch_bounds__(256)
k_moe(const float* __restrict__ fc1b, const float* __restrict__ fc2b) {
    int e    = blockIdx.x >> 9;
    int tile = blockIdx.x & 511;
    int cnt  = g_cnt[e];
    int row0 = tile << 7;
    if (row0 >= cnt) return;

    extern __shared__ char sm[];
    unsigned sb = smem_u32(sm);
    __half* Xs = (__half*)(sm + S2_X);
    __half* W2 = (__half*)(sm + S2_W2);
    __half* Hs = (__half*)(sm + S2_H);
    int*   slot_s = (int*)(sm + S2_SLOT);
    float* gate_s = (float*)(sm + S2_GATE);

    int tid = threadIdx.x;
    int wid = tid >> 5, lt = tid & 31;
    int qr = lt >> 2, qc = lt & 3;
    int m0 = wid * 16;

    const __half* w1g = g_w1t + (size_t)e * NHF * NCH;
    const __half* w2g = g_w2t + (size_t)e * NHF * NCH;

    // prefetch W1 chunk 0 into buffer 0
    {
        unsigned d = sb + S2_W1;
#pragma unroll
        for (int it = 0; it < 4; it++) {
            int u = tid + it * 256;              // 0..1023
            int n1 = u >> 4, k16 = u & 15;
            CP16(d + (unsigned)(n1 * 136 + k16 * 8) * 2, w1g + n1 * NCH + k16 * 8);
        }
        CP_COMMIT();
    }

    if (tid < 128) {
        int r = row0 + tid;
        if (r < cnt) { slot_s[tid] = g_list[e * LCAP + r]; gate_s[tid] = g_gate[e * LCAP + r]; }
        else         { slot_s[tid] = -1; gate_s[tid] = 0.f; }
    }
    __syncthreads();

    // gather X -> fp16
#pragma unroll
    for (int it = 0; it < 8; it++) {
        int idx = tid + it * 256;
        int r = idx >> 4, c8 = idx & 15;
        float v[8];
        int s = slot_s[r];
        if (s >= 0) {
            const float4* src = (const float4*)(g_xf + (size_t)(s >> 1) * NCH + c8 * 8);
            float4 a = src[0], b = src[1];
            v[0]=a.x; v[1]=a.y; v[2]=a.z; v[3]=a.w; v[4]=b.x; v[5]=b.y; v[6]=b.z; v[7]=b.w;
        } else {
#pragma unroll
            for (int q = 0; q < 8; q++) v[q] = 0.f;
        }
        uint4 U;
        U.x = pack2h(v[0], v[1]);
        U.y = pack2h(v[2], v[3]);
        U.z = pack2h(v[4], v[5]);
        U.w = pack2h(v[6], v[7]);
        *(uint4*)(Xs + r * 136 + c8 * 8) = U;
    }

    float acc2[16][4];
#pragma unroll
    for (int j = 0; j < 16; j++)
#pragma unroll
        for (int q = 0; q < 4; q++) acc2[j][q] = 0.f;

    for (int jc = 0; jc < 8; jc++) {
        int cur = jc & 1;
        __half* W1 = (__half*)(sm + S2_W1 + cur * 17408);

        // issue W2(jc) async
        {
            unsigned d2 = sb + S2_W2;
            const __half* s2 = w2g + jc * 8192;
#pragma unroll
            for (int it = 0; it < 4; it++) {
                int u = tid + it * 256;
                int n2 = u >> 3, k8 = u & 7;
                CP16(d2 + (unsigned)(n2 * 72 + k8 * 8) * 2, s2 + n2 * 64 + k8 * 8);
            }
            CP_COMMIT();
        }
        CP_WAIT(1);              // W1(jc) arrived
        __syncthreads();

        // GEMM1: [128 x 64] = X * W1^T  (single-pass fp16)
        float acc1[8][4];
#pragma unroll
        for (int j = 0; j < 8; j++)
#pragma unroll
            for (int q = 0; q < 4; q++) acc1[j][q] = 0.f;

#pragma unroll
        for (int kt = 0; kt < 8; kt++) {
            int row = m0 + qr, col = kt * 16 + qc * 2;
            unsigned a[4];
            a[0] = *(const unsigned*)(Xs + row * 136 + col);
            a[1] = *(const unsigned*)(Xs + (row + 8) * 136 + col);
            a[2] = *(const unsigned*)(Xs + row * 136 + col + 8);
            a[3] = *(const unsigned*)(Xs + (row + 8) * 136 + col + 8);
#pragma unroll
            for (int j = 0; j < 8; j++) {
                int n = j * 8 + qr;
                unsigned b[2];
                b[0] = *(const unsigned*)(W1 + n * 136 + col);
                b[1] = *(const unsigned*)(W1 + n * 136 + col + 8);
                mma16816h(acc1[j], a, b);
            }
        }

        // bias + gelu -> H (fp16)
#pragma unroll
        for (int j = 0; j < 8; j++) {
            int n = j * 8 + qc * 2;
            float2 b1 = *(const float2*)(fc1b + e * NHF + jc * 64 + n);
            *(unsigned*)(Hs + (m0 + qr) * 72 + n) =
                pack2h(gelu_exact(acc1[j][0] + b1.x), gelu_exact(acc1[j][1] + b1.y));
            *(unsigned*)(Hs + (m0 + qr + 8) * 72 + n) =
                pack2h(gelu_exact(acc1[j][2] + b1.x), gelu_exact(acc1[j][3] + b1.y));
        }
        CP_WAIT(0);              // W2(jc) arrived
        __syncthreads();         // H visible + W2 visible

        // prefetch W1(jc+1) during GEMM2
        if (jc < 7) {
            unsigned d = sb + S2_W1 + (1 - cur) * 17408;
            const __half* s1 = w1g + (jc + 1) * 64 * NCH;
#pragma unroll
            for (int it = 0; it < 4; it++) {
                int u = tid + it * 256;
                int n1 = u >> 4, k16 = u & 15;
                CP16(d + (unsigned)(n1 * 136 + k16 * 8) * 2, s1 + n1 * NCH + k16 * 8);
            }
            CP_COMMIT();
        }

        // GEMM2: [128 x 128] += H * W2^T
#pragma unroll
        for (int kt = 0; kt < 4; kt++) {
            int row = m0 + qr, col = kt * 16 + qc * 2;
            unsigned a[4];
            a[0] = *(const unsigned*)(Hs + row * 72 + col);
            a[1] = *(const unsigned*)(Hs + (row + 8) * 72 + col);
            a[2] = *(const unsigned*)(Hs + row * 72 + col + 8);
            a[3] = *(const unsigned*)(Hs + (row + 8) * 72 + col + 8);
#pragma unroll
            for (int j = 0; j < 16; j++) {
                int n = j * 8 + qr;
                unsigned b[2];
                b[0] = *(const unsigned*)(W2 + n * 72 + col);
                b[1] = *(const unsigned*)(W2 + n * 72 + col + 8);
                mma16816h(acc2[j], a, b);
            }
        }
        __syncthreads();         // protect H + W2 for next chunk
    }

    // epilogue: gate * exp(out + b2) -> g_res
    int mA = m0 + qr, mB = m0 + qr + 8;
    int sA = slot_s[mA], sB = slot_s[mB];
    float gA = gate_s[mA], gB = gate_s[mB];
#pragma unroll
    for (int j = 0; j < 16; j++) {
        int c = j * 8 + qc * 2;
        float2 b2 = *(const float2*)(fc2b + e * NCH + c);
        if (sA >= 0) {
            float2 o;
            o.x = gA * expf(acc2[j][0] + b2.x);
            o.y = gA * expf(acc2[j][1] + b2.y);
            *(float2*)(g_res + (size_t)sA * NCH + c) = o;
        }
        if (sB >= 0) {
            float2 o;
            o.x = gB * expf(acc2[j][2] + b2.x);
            o.y = gB * expf(acc2[j][3] + b2.y);
            *(float2*)(g_res + (size_t)sB * NCH + c) = o;
        }
    }
}

// ---------------- kernel 6: combine + log + transpose back ----------------
__global__ void k_out(float* __restrict__ out) {
    __shared__ float tile[32][33];
    int bh = blockIdx.z;
    int b = bh / NH, h = bh % NH;
    int c0 = blockIdx.x * 32, w0 = blockIdx.y * 32;
    int tx = threadIdx.x, ty = threadIdx.y;
    for (int i = ty; i < 32; i += 8) {
        size_t base = (size_t)(b * NHW + h * NW + w0 + i) * 2 * NCH;
        float v = g_res[base + c0 + tx] + g_res[base + NCH + c0 + tx];
        if (v == 0.f) v = 2.2204460492503131e-16f;
        tile[i][tx] = logf(v);
    }
    __syncthreads();
    for (int i = ty; i < 32; i += 8)
        out[(((size_t)b * NCH + c0 + i) * NH + h) * NW + w0 + tx] = tile[tx][i];
}

// ---------------- launch ----------------
extern "C" void kernel_launch(void* const* d_in, const int* in_sizes, int n_in,
                              void* d_out, int out_size) {
    (void)in_sizes; (void)n_in;
    const float* x       = (const float*)d_in[0];
    const float* prompt  = (const float*)d_in[1];
    const float* de_cls  = (const float*)d_in[2];
    const float* w_g     = (const float*)d_in[3];
    const float* gboost  = (const float*)d_in[4];
    const float* degra_w = (const float*)d_in[5];
    const float* degra_b = (const float*)d_in[6];
    const float* fc1w    = (const float*)d_in[7];
    const float* fc1b    = (const float*)d_in[8];
    const float* fc2w    = (const float*)d_in[9];
    const float* fc2b    = (const float*)d_in[10];
    float* out = (float*)d_out;

    k_init<<<1, 32>>>(prompt, de_cls, w_g, gboost, degra_w, degra_b);
    k_gate<<<GBLK, 256>>>(x, w_g, out, out_size);

    dim3 tb(32, 8);
    k_trans<<<dim3(NCH / 32, NW / 32, NB * NH), tb>>>(x);
    k_prep<<<3072, 256>>>(fc1w, fc2w);

    cudaFuncSetAttribute(k_moe, cudaFuncAttributeMaxDynamicSharedMemorySize, S2_BYTES);
    k_moe<<<NE * 512, 256, S2_BYTES>>>(fc1b, fc2b);

    k_out<<<dim3(NCH / 32, NW / 32, NB * NH), tb>>>(out);
}

// round 7
// speedup vs baseline: 3.3328x; 1.0877x over previous
#include <cuda_runtime.h>
#include <cuda_bf16.h>
#include <cuda_fp16.h>
#include <math.h>

// ---------------- problem constants ----------------
#define NB   2
#define NCH  128
#define NH   128
#define NW   128
#define NE   6
#define ND   6
#define NHF  512
#define NHW  (NH*NW)        // 16384
#define NTOK (NB*NH*NW)     // 32768
#define NOUT (NTOK*NCH)
#define GBLK 128            // gate blocks (256 tokens each)
#define LCAP (2*NTOK)       // per-expert list capacity

// ---------------- scratch ----------------
__device__ float g_xf[NTOK * NCH];
__device__ float g_res[NTOK * 2 * NCH];
__device__ int   g_list[NE * LCAP];
__device__ float g_gate[NE * LCAP];
__device__ int   g_cnt[NE];
__device__ float g_bias[NB * NE];
__device__ float g_partW[GBLK * NE];
__device__ float g_partC[GBLK * NE];
__device__ unsigned g_done;

// fp16 weights, B layout [n][k]
__device__ __align__(16) __half g_w1t[NE * NHF * NCH];
__device__ __align__(16) __half g_w2t[NE * NHF * NCH];

__device__ __forceinline__ float gelu_exact(float z) {
    return 0.5f * z * (1.0f + erff(z * 0.7071067811865475f));
}
__device__ __forceinline__ unsigned pack2h(float a0, float a1) {
    __half2 h = __floats2half2_rn(a0, a1);
    return *(unsigned*)&h;
}
__device__ __forceinline__ void mma16816h(float* c, const unsigned* a, const unsigned* b) {
    asm volatile("mma.sync.aligned.m16n8k16.row.col.f32.f16.f16.f32 "
                 "{%0,%1,%2,%3}, {%4,%5,%6,%7}, {%8,%9}, {%0,%1,%2,%3};"
                 : "+f"(c[0]), "+f"(c[1]), "+f"(c[2]), "+f"(c[3])
                 : "r"(a[0]), "r"(a[1]), "r"(a[2]), "r"(a[3]),
                   "r"(b[0]), "r"(b[1]));
}
__device__ __forceinline__ void ldm_x4(unsigned* r, unsigned addr) {
    asm volatile("ldmatrix.sync.aligned.m8n8.x4.shared.b16 {%0,%1,%2,%3}, [%4];"
                 : "=r"(r[0]), "=r"(r[1]), "=r"(r[2]), "=r"(r[3]) : "r"(addr));
}
__device__ __forceinline__ unsigned smem_u32(const void* p) {
    unsigned a;
    asm("{ .reg .u64 t; cvta.to.shared.u64 t, %1; cvt.u32.u64 %0, t; }" : "=r"(a) : "l"(p));
    return a;
}
#define CP16(dst, src) \
    asm volatile("cp.async.cg.shared.global [%0], [%1], 16;" :: "r"(dst), "l"(src))
#define CP_COMMIT() asm volatile("cp.async.commit_group;" ::: "memory")
#define CP_WAIT(n)  asm volatile("cp.async.wait_group %0;" :: "n"(n) : "memory")

// ---------------- kernel 1: init ----------------
__global__ void k_init(const float* __restrict__ prompt,
                       const float* __restrict__ de_cls,
                       const float* __restrict__ w_g,
                       const float* __restrict__ gboost,
                       const float* __restrict__ degra_w,
                       const float* __restrict__ degra_b) {
    int t = threadIdx.x;
    if (t < NB * NE) {
        int b = t / NE, e = t % NE;
        float s1 = 0.f;
        for (int c = 0; c < NCH; c++)
            s1 += prompt[b * NCH + c] * w_g[(NCH + c) * NE + e];
        float s2 = 0.f;
        for (int d = 0; d < ND; d++)
            s2 += de_cls[b * ND + d] * degra_w[d * NE + e];
        g_bias[t] = s1 + gboost[0] * (s2 + degra_b[e]);
    }
    if (t < NE) g_cnt[t] = 0;
    if (t == 31) g_done = 0;
}

// ---------------- kernel 2: transpose x -> xf ----------------
__global__ void k_trans(const float* __restrict__ x) {
    __shared__ float tile[32][33];
    int bh = blockIdx.z;
    int b = bh / NH, h = bh % NH;
    int c0 = blockIdx.x * 32, w0 = blockIdx.y * 32;
    int tx = threadIdx.x, ty = threadIdx.y;
    for (int i = ty; i < 32; i += 8)
        tile[i][tx] = x[(((size_t)b * NCH + c0 + i) * NH + h) * NW + w0 + tx];
    __syncthreads();
    for (int i = ty; i < 32; i += 8)
        g_xf[((size_t)(b * NHW + h * NW + w0 + i)) * NCH + c0 + tx] = tile[tx][i];
}

// ---------------- kernel 3: gating (coalesced from x) + fused loss ----------
__global__ void __launch_bounds__(256)
k_gate(const float* __restrict__ x, const float* __restrict__ w_g,
       float* __restrict__ out, int out_size) {
    __shared__ float wg_s[NCH * NE];
    __shared__ float wsum[8][NE];
    __shared__ int   wcnt[8][NE];
    __shared__ unsigned is_last_s;
    int tid = threadIdx.x;
    for (int i = tid; i < NCH * NE; i += 256) wg_s[i] = w_g[i];
    __syncthreads();

    int n = blockIdx.x * 256 + tid;
    int b = n >> 14;
    int hw = n & (NHW - 1);
    float acc[NE];
#pragma unroll
    for (int e = 0; e < NE; e++) acc[e] = g_bias[b * NE + e];
    const float* xb = x + (size_t)b * NCH * NHW + hw;
#pragma unroll 4
    for (int c = 0; c < NCH; c++) {
        float xv = xb[(size_t)c * NHW];
#pragma unroll
        for (int e = 0; e < NE; e++) acc[e] += xv * wg_s[c * NE + e];
    }
    int i0 = 0; float v0 = acc[0];
#pragma unroll
    for (int e = 1; e < NE; e++) if (acc[e] > v0) { v0 = acc[e]; i0 = e; }
    int i1 = (i0 == 0) ? 1 : 0; float v1 = acc[i1];
#pragma unroll
    for (int e = 0; e < NE; e++)
        if (e != i0 && acc[e] > v1) { v1 = acc[e]; i1 = e; }
    float g0 = 1.f / (1.f + expf(v1 - v0));
    float g1 = 1.f - g0;

    int p0 = atomicAdd(&g_cnt[i0], 1);
    g_list[i0 * LCAP + p0] = n * 2 + 0;
    g_gate[i0 * LCAP + p0] = g0;
    int p1 = atomicAdd(&g_cnt[i1], 1);
    g_list[i1 * LCAP + p1] = n * 2 + 1;
    g_gate[i1 * LCAP + p1] = g1;

    int warp = tid >> 5, lane = tid & 31;
#pragma unroll
    for (int e = 0; e < NE; e++) {
        float gv = (i0 == e ? g0 : 0.f) + (i1 == e ? g1 : 0.f);
        int   cv = (i0 == e) + (i1 == e);
        for (int off = 16; off; off >>= 1) {
            gv += __shfl_down_sync(0xffffffffu, gv, off);
            cv += __shfl_down_sync(0xffffffffu, cv, off);
        }
        if (lane == 0) { wsum[warp][e] = gv; wcnt[warp][e] = cv; }
    }
    __syncthreads();
    if (tid < NE) {
        float s = 0.f; int c = 0;
#pragma unroll
        for (int w = 0; w < 8; w++) { s += wsum[w][tid]; c += wcnt[w][tid]; }
        g_partW[blockIdx.x * NE + tid] = s;
        g_partC[blockIdx.x * NE + tid] = (float)c;
    }
    __threadfence();
    __syncthreads();
    if (tid == 0) is_last_s = (atomicAdd(&g_done, 1u) == GBLK - 1);
    __syncthreads();
    if (is_last_s) {
        if (warp < NE) {
            float sW = g_partW[lane * NE + warp] + g_partW[(lane + 32) * NE + warp]
                     + g_partW[(lane + 64) * NE + warp] + g_partW[(lane + 96) * NE + warp];
            float sC = g_partC[lane * NE + warp] + g_partC[(lane + 32) * NE + warp]
                     + g_partC[(lane + 64) * NE + warp] + g_partC[(lane + 96) * NE + warp];
            for (int off = 16; off; off >>= 1) {
                sW += __shfl_down_sync(0xffffffffu, sW, off);
                sC += __shfl_down_sync(0xffffffffu, sC, off);
            }
            if (lane == 0) { wsum[0][warp] = sW; wsum[1][warp] = sC; }
        }
        __syncthreads();
        if (tid == 0 && out_size > NOUT) {
            float mW = 0.f, mC = 0.f;
            for (int e = 0; e < NE; e++) { mW += wsum[0][e]; mC += wsum[1][e]; }
            mW /= NE; mC /= NE;
            float vW = 0.f, vC = 0.f;
            for (int e = 0; e < NE; e++) {
                vW += (wsum[0][e] - mW) * (wsum[0][e] - mW);
                vC += (wsum[1][e] - mC) * (wsum[1][e] - mC);
            }
            vW /= (NE - 1); vC /= (NE - 1);
            out[NOUT] = vW / (mW * mW + 1e-10f) + vC / (mC * mC + 1e-10f);
        }
    }
}

// ---------------- kernel 4b: weight prep (fp16, transpose to [n][k]) --------
#define W1ELEM (NE * NHF * NCH)
__global__ void k_prep(const float* __restrict__ fc1w, const float* __restrict__ fc2w) {
    int idx = blockIdx.x * 256 + threadIdx.x;
    if (idx < W1ELEM) {
        int e = idx >> 16, rem = idx & 65535;
        int n = rem >> 7, k = rem & 127;
        g_w1t[idx] = __float2half_rn(fc1w[((size_t)e * NCH + k) * NHF + n]);
    } else {
        int j = idx - W1ELEM;
        if (j < W1ELEM) {
            int e = j >> 16, rem = j & 65535;
            int jc = rem >> 13, r2 = rem & 8191;
            int c = r2 >> 6, k = r2 & 63;
            g_w2t[j] = __float2half_rn(fc2w[((size_t)e * NHF + jc * 64 + k) * NCH + c]);
        }
    }
}

// ---------------- kernel 5: single-pass fp16 mma MoE (ldmatrix) --------------
// SMEM map (bytes):
#define S2_X     0                     // [128][136] half = 34816
#define S2_W1    34816                 // 2 buffers x [64][136] half = 2*17408
#define S2_W2    69632                 // [128][72] half = 18432
#define S2_H     88064                 // [128][72] half = 18432
#define S2_SLOT  106496
#define S2_GATE  107008
#define S2_BYTES 107520

__global__ void __launch_bounds__(256, 2)
k_moe(const float* __restrict__ fc1b, const float* __restrict__ fc2b) {
    int e    = blockIdx.x >> 9;
    int tile = blockIdx.x & 511;
    int cnt  = g_cnt[e];
    int row0 = tile << 7;
    if (row0 >= cnt) return;

    extern __shared__ char sm[];
    unsigned sb = smem_u32(sm);
    __half* Xs = (__half*)(sm + S2_X);
    __half* Hs = (__half*)(sm + S2_H);
    int*   slot_s = (int*)(sm + S2_SLOT);
    float* gate_s = (float*)(sm + S2_GATE);

    int tid = threadIdx.x;
    int wid = tid >> 5, lt = tid & 31;
    int qr = lt >> 2, qc = lt & 3;
    int m0 = wid * 16;
    // ldmatrix per-lane address terms: row = (lt&15), col-half-block = (lt&16)?8:0
    int lrow = lt & 15;
    int lcol = (lt & 16) >> 1;        // 0 or 8 (halfs)

    const __half* w1g = g_w1t + (size_t)e * NHF * NCH;
    const __half* w2g = g_w2t + (size_t)e * NHF * NCH;

    // prefetch W1 chunk 0 into buffer 0
    {
        unsigned d = sb + S2_W1;
#pragma unroll
        for (int it = 0; it < 4; it++) {
            int u = tid + it * 256;              // 0..1023
            int n1 = u >> 4, k16 = u & 15;
            CP16(d + (unsigned)(n1 * 136 + k16 * 8) * 2, w1g + n1 * NCH + k16 * 8);
        }
        CP_COMMIT();
    }

    if (tid < 128) {
        int r = row0 + tid;
        if (r < cnt) { slot_s[tid] = g_list[e * LCAP + r]; gate_s[tid] = g_gate[e * LCAP + r]; }
        else         { slot_s[tid] = -1; gate_s[tid] = 0.f; }
    }
    __syncthreads();

    // gather X -> fp16
#pragma unroll
    for (int it = 0; it < 8; it++) {
        int idx = tid + it * 256;
        int r = idx >> 4, c8 = idx & 15;
        float v[8];
        int s = slot_s[r];
        if (s >= 0) {
            const float4* src = (const float4*)(g_xf + (size_t)(s >> 1) * NCH + c8 * 8);
            float4 a = src[0], b = src[1];
            v[0]=a.x; v[1]=a.y; v[2]=a.z; v[3]=a.w; v[4]=b.x; v[5]=b.y; v[6]=b.z; v[7]=b.w;
        } else {
#pragma unroll
            for (int q = 0; q < 8; q++) v[q] = 0.f;
        }
        uint4 U;
        U.x = pack2h(v[0], v[1]);
        U.y = pack2h(v[2], v[3]);
        U.z = pack2h(v[4], v[5]);
        U.w = pack2h(v[6], v[7]);
        *(uint4*)(Xs + r * 136 + c8 * 8) = U;
    }

    float acc2[16][4];
#pragma unroll
    for (int j = 0; j < 16; j++)
#pragma unroll
        for (int q = 0; q < 4; q++) acc2[j][q] = 0.f;

    // per-lane ldmatrix base addresses (bytes)
    unsigned aX  = sb + S2_X  + (unsigned)((m0 + lrow) * 136 + lcol) * 2;
    unsigned aH  = sb + S2_H  + (unsigned)((m0 + lrow) * 72  + lcol) * 2;
    unsigned bW2 = sb + S2_W2 + (unsigned)(lrow * 72 + lcol) * 2;

    for (int jc = 0; jc < 8; jc++) {
        int cur = jc & 1;
        unsigned bW1 = sb + S2_W1 + cur * 17408 + (unsigned)(lrow * 136 + lcol) * 2;

        // issue W2(jc) async
        {
            unsigned d2 = sb + S2_W2;
            const __half* s2 = w2g + jc * 8192;
#pragma unroll
            for (int it = 0; it < 4; it++) {
                int u = tid + it * 256;
                int n2 = u >> 3, k8 = u & 7;
                CP16(d2 + (unsigned)(n2 * 72 + k8 * 8) * 2, s2 + n2 * 64 + k8 * 8);
            }
            CP_COMMIT();
        }
        CP_WAIT(1);              // W1(jc) arrived
        __syncthreads();

        // GEMM1: [128 x 64] = X * W1^T  (ldmatrix fragments)
        float acc1[8][4];
#pragma unroll
        for (int j = 0; j < 8; j++)
#pragma unroll
            for (int q = 0; q < 4; q++) acc1[j][q] = 0.f;

#pragma unroll
        for (int kt = 0; kt < 8; kt++) {
            unsigned a[4];
            ldm_x4(a, aX + kt * 32);
#pragma unroll
            for (int j2 = 0; j2 < 4; j2++) {
                unsigned r[4];
                ldm_x4(r, bW1 + (unsigned)(j2 * 16 * 136) * 2 + kt * 32);
                unsigned b0[2] = { r[0], r[2] };
                unsigned b1[2] = { r[1], r[3] };
                mma16816h(acc1[2 * j2],     a, b0);
                mma16816h(acc1[2 * j2 + 1], a, b1);
            }
        }

        // bias + gelu -> H (fp16)
#pragma unroll
        for (int j = 0; j < 8; j++) {
            int n = j * 8 + qc * 2;
            float2 b1 = *(const float2*)(fc1b + e * NHF + jc * 64 + n);
            *(unsigned*)(Hs + (m0 + qr) * 72 + n) =
                pack2h(gelu_exact(acc1[j][0] + b1.x), gelu_exact(acc1[j][1] + b1.y));
            *(unsigned*)(Hs + (m0 + qr + 8) * 72 + n) =
                pack2h(gelu_exact(acc1[j][2] + b1.x), gelu_exact(acc1[j][3] + b1.y));
        }
        CP_WAIT(0);              // W2(jc) arrived
        __syncthreads();         // H visible + W2 visible

        // prefetch W1(jc+1) during GEMM2
        if (jc < 7) {
            unsigned d = sb + S2_W1 + (1 - cur) * 17408;
            const __half* s1 = w1g + (jc + 1) * 64 * NCH;
#pragma unroll
            for (int it = 0; it < 4; it++) {
                int u = tid + it * 256;
                int n1 = u >> 4, k16 = u & 15;
                CP16(d + (unsigned)(n1 * 136 + k16 * 8) * 2, s1 + n1 * NCH + k16 * 8);
            }
            CP_COMMIT();
        }

        // GEMM2: [128 x 128] += H * W2^T  (ldmatrix fragments)
#pragma unroll
        for (int kt = 0; kt < 4; kt++) {
            unsigned a[4];
            ldm_x4(a, aH + kt * 32);
#pragma unroll
            for (int j2 = 0; j2 < 8; j2++) {
                unsigned r[4];
                ldm_x4(r, bW2 + (unsigned)(j2 * 16 * 72) * 2 + kt * 32);
                unsigned b0[2] = { r[0], r[2] };
                unsigned b1[2] = { r[1], r[3] };
                mma16816h(acc2[2 * j2],     a, b0);
                mma16816h(acc2[2 * j2 + 1], a, b1);
            }
        }
        __syncthreads();         // protect H + W2 for next chunk
    }

    // epilogue: gate * exp(out + b2) -> g_res
    int mA = m0 + qr, mB = m0 + qr + 8;
    int sA = slot_s[mA], sB = slot_s[mB];
    float gA = gate_s[mA], gB = gate_s[mB];
#pragma unroll
    for (int j = 0; j < 16; j++) {
        int c = j * 8 + qc * 2;
        float2 b2 = *(const float2*)(fc2b + e * NCH + c);
        if (sA >= 0) {
            float2 o;
            o.x = gA * expf(acc2[j][0] + b2.x);
            o.y = gA * expf(acc2[j][1] + b2.y);
            *(float2*)(g_res + (size_t)sA * NCH + c) = o;
        }
        if (sB >= 0) {
            float2 o;
            o.x = gB * expf(acc2[j][2] + b2.x);
            o.y = gB * expf(acc2[j][3] + b2.y);
            *(float2*)(g_res + (size_t)sB * NCH + c) = o;
        }
    }
}

// ---------------- kernel 6: combine + log + transpose back ----------------
__global__ void k_out(float* __restrict__ out) {
    __shared__ float tile[32][33];
    int bh = blockIdx.z;
    int b = bh / NH, h = bh % NH;
    int c0 = blockIdx.x * 32, w0 = blockIdx.y * 32;
    int tx = threadIdx.x, ty = threadIdx.y;
    for (int i = ty; i < 32; i += 8) {
        size_t base = (size_t)(b * NHW + h * NW + w0 + i) * 2 * NCH;
        float v = g_res[base + c0 + tx] + g_res[base + NCH + c0 + tx];
        if (v == 0.f) v = 2.2204460492503131e-16f;
        tile[i][tx] = logf(v);
    }
    __syncthreads();
    for (int i = ty; i < 32; i += 8)
        out[(((size_t)b * NCH + c0 + i) * NH + h) * NW + w0 + tx] = tile[tx][i];
}

// ---------------- launch ----------------
extern "C" void kernel_launch(void* const* d_in, const int* in_sizes, int n_in,
                              void* d_out, int out_size) {
    (void)in_sizes; (void)n_in;
    const float* x       = (const float*)d_in[0];
    const float* prompt  = (const float*)d_in[1];
    const float* de_cls  = (const float*)d_in[2];
    const float* w_g     = (const float*)d_in[3];
    const float* gboost  = (const float*)d_in[4];
    const float* degra_w = (const float*)d_in[5];
    const float* degra_b = (const float*)d_in[6];
    const float* fc1w    = (const float*)d_in[7];
    const float* fc1b    = (const float*)d_in[8];
    const float* fc2w    = (const float*)d_in[9];
    const float* fc2b    = (const float*)d_in[10];
    float* out = (float*)d_out;

    k_init<<<1, 32>>>(prompt, de_cls, w_g, gboost, degra_w, degra_b);
    k_gate<<<GBLK, 256>>>(x, w_g, out, out_size);

    dim3 tb(32, 8);
    k_trans<<<dim3(NCH / 32, NW / 32, NB * NH), tb>>>(x);
    k_prep<<<3072, 256>>>(fc1w, fc2w);

    cudaFuncSetAttribute(k_moe, cudaFuncAttributeMaxDynamicSharedMemorySize, S2_BYTES);
    k_moe<<<NE * 512, 256, S2_BYTES>>>(fc1b, fc2b);

    k_out<<<dim3(NCH / 32, NW / 32, NB * NH), tb>>>(out);
}

// round 8
// speedup vs baseline: 3.4008x; 1.0204x over previous
#include <cuda_runtime.h>
#include <cuda_bf16.h>
#include <cuda_fp16.h>
#include <math.h>

// ---------------- problem constants ----------------
#define NB   2
#define NCH  128
#define NH   128
#define NW   128
#define NE   6
#define ND   6
#define NHF  512
#define NHW  (NH*NW)        // 16384
#define NTOK (NB*NH*NW)     // 32768
#define NOUT (NTOK*NCH)
#define GBLK 128            // gate blocks (256 tokens each)
#define LCAP (2*NTOK)       // per-expert list capacity

// ---------------- scratch ----------------
__device__ float g_xf[NTOK * NCH];
__device__ float g_res[NTOK * 2 * NCH];
__device__ int   g_list[NE * LCAP];
__device__ float g_gate[NE * LCAP];
__device__ int   g_cnt[NE];
__device__ float g_bias[NB * NE];
__device__ float g_partW[GBLK * NE];
__device__ float g_partC[GBLK * NE];
__device__ unsigned g_done;

// fp16 weights, B layout [n][k]
__device__ __align__(16) __half g_w1t[NE * NHF * NCH];
__device__ __align__(16) __half g_w2t[NE * NHF * NCH];

__device__ __forceinline__ float gelu_exact(float z) {
    return 0.5f * z * (1.0f + erff(z * 0.7071067811865475f));
}
__device__ __forceinline__ unsigned pack2h(float a0, float a1) {
    __half2 h = __floats2half2_rn(a0, a1);
    return *(unsigned*)&h;
}
__device__ __forceinline__ void mma16816h(float* c, const unsigned* a, const unsigned* b) {
    asm volatile("mma.sync.aligned.m16n8k16.row.col.f32.f16.f16.f32 "
                 "{%0,%1,%2,%3}, {%4,%5,%6,%7}, {%8,%9}, {%0,%1,%2,%3};"
                 : "+f"(c[0]), "+f"(c[1]), "+f"(c[2]), "+f"(c[3])
                 : "r"(a[0]), "r"(a[1]), "r"(a[2]), "r"(a[3]),
                   "r"(b[0]), "r"(b[1]));
}
__device__ __forceinline__ void ldm_x4(unsigned* r, unsigned addr) {
    asm volatile("ldmatrix.sync.aligned.m8n8.x4.shared.b16 {%0,%1,%2,%3}, [%4];"
                 : "=r"(r[0]), "=r"(r[1]), "=r"(r[2]), "=r"(r[3]) : "r"(addr));
}
__device__ __forceinline__ unsigned smem_u32(const void* p) {
    unsigned a;
    asm("{ .reg .u64 t; cvta.to.shared.u64 t, %1; cvt.u32.u64 %0, t; }" : "=r"(a) : "l"(p));
    return a;
}
#define CP16(dst, src) \
    asm volatile("cp.async.cg.shared.global [%0], [%1], 16;" :: "r"(dst), "l"(src))
#define CP_COMMIT() asm volatile("cp.async.commit_group;" ::: "memory")
#define CP_WAIT(n)  asm volatile("cp.async.wait_group %0;" :: "n"(n) : "memory")

// ---------------- kernel 1: init ----------------
__global__ void k_init(const float* __restrict__ prompt,
                       const float* __restrict__ de_cls,
                       const float* __restrict__ w_g,
                       const float* __restrict__ gboost,
                       const float* __restrict__ degra_w,
                       const float* __restrict__ degra_b) {
    int t = threadIdx.x;
    if (t < NB * NE) {
        int b = t / NE, e = t % NE;
        float s1 = 0.f;
        for (int c = 0; c < NCH; c++)
            s1 += prompt[b * NCH + c] * w_g[(NCH + c) * NE + e];
        float s2 = 0.f;
        for (int d = 0; d < ND; d++)
            s2 += de_cls[b * ND + d] * degra_w[d * NE + e];
        g_bias[t] = s1 + gboost[0] * (s2 + degra_b[e]);
    }
    if (t < NE) g_cnt[t] = 0;
    if (t == 31) g_done = 0;
}

// ---------------- kernel 2: transpose x -> xf ----------------
__global__ void k_trans(const float* __restrict__ x) {
    __shared__ float tile[32][33];
    int bh = blockIdx.z;
    int b = bh / NH, h = bh % NH;
    int c0 = blockIdx.x * 32, w0 = blockIdx.y * 32;
    int tx = threadIdx.x, ty = threadIdx.y;
    for (int i = ty; i < 32; i += 8)
        tile[i][tx] = x[(((size_t)b * NCH + c0 + i) * NH + h) * NW + w0 + tx];
    __syncthreads();
    for (int i = ty; i < 32; i += 8)
        g_xf[((size_t)(b * NHW + h * NW + w0 + i)) * NCH + c0 + tx] = tile[tx][i];
}

// ---------------- kernel 3: gating (coalesced from x) + fused loss ----------
__global__ void __launch_bounds__(256)
k_gate(const float* __restrict__ x, const float* __restrict__ w_g,
       float* __restrict__ out, int out_size) {
    __shared__ float wg_s[NCH * NE];
    __shared__ float wsum[8][NE];
    __shared__ int   wcnt[8][NE];
    __shared__ unsigned is_last_s;
    int tid = threadIdx.x;
    for (int i = tid; i < NCH * NE; i += 256) wg_s[i] = w_g[i];
    __syncthreads();

    int n = blockIdx.x * 256 + tid;
    int b = n >> 14;
    int hw = n & (NHW - 1);
    float acc[NE];
#pragma unroll
    for (int e = 0; e < NE; e++) acc[e] = g_bias[b * NE + e];
    const float* xb = x + (size_t)b * NCH * NHW + hw;
#pragma unroll 4
    for (int c = 0; c < NCH; c++) {
        float xv = xb[(size_t)c * NHW];
#pragma unroll
        for (int e = 0; e < NE; e++) acc[e] += xv * wg_s[c * NE + e];
    }
    int i0 = 0; float v0 = acc[0];
#pragma unroll
    for (int e = 1; e < NE; e++) if (acc[e] > v0) { v0 = acc[e]; i0 = e; }
    int i1 = (i0 == 0) ? 1 : 0; float v1 = acc[i1];
#pragma unroll
    for (int e = 0; e < NE; e++)
        if (e != i0 && acc[e] > v1) { v1 = acc[e]; i1 = e; }
    float g0 = 1.f / (1.f + expf(v1 - v0));
    float g1 = 1.f - g0;

    int p0 = atomicAdd(&g_cnt[i0], 1);
    g_list[i0 * LCAP + p0] = n * 2 + 0;
    g_gate[i0 * LCAP + p0] = g0;
    int p1 = atomicAdd(&g_cnt[i1], 1);
    g_list[i1 * LCAP + p1] = n * 2 + 1;
    g_gate[i1 * LCAP + p1] = g1;

    int warp = tid >> 5, lane = tid & 31;
#pragma unroll
    for (int e = 0; e < NE; e++) {
        float gv = (i0 == e ? g0 : 0.f) + (i1 == e ? g1 : 0.f);
        int   cv = (i0 == e) + (i1 == e);
        for (int off = 16; off; off >>= 1) {
            gv += __shfl_down_sync(0xffffffffu, gv, off);
            cv += __shfl_down_sync(0xffffffffu, cv, off);
        }
        if (lane == 0) { wsum[warp][e] = gv; wcnt[warp][e] = cv; }
    }
    __syncthreads();
    if (tid < NE) {
        float s = 0.f; int c = 0;
#pragma unroll
        for (int w = 0; w < 8; w++) { s += wsum[w][tid]; c += wcnt[w][tid]; }
        g_partW[blockIdx.x * NE + tid] = s;
        g_partC[blockIdx.x * NE + tid] = (float)c;
    }
    __threadfence();
    __syncthreads();
    if (tid == 0) is_last_s = (atomicAdd(&g_done, 1u) == GBLK - 1);
    __syncthreads();
    if (is_last_s) {
        if (warp < NE) {
            float sW = g_partW[lane * NE + warp] + g_partW[(lane + 32) * NE + warp]
                     + g_partW[(lane + 64) * NE + warp] + g_partW[(lane + 96) * NE + warp];
            float sC = g_partC[lane * NE + warp] + g_partC[(lane + 32) * NE + warp]
                     + g_partC[(lane + 64) * NE + warp] + g_partC[(lane + 96) * NE + warp];
            for (int off = 16; off; off >>= 1) {
                sW += __shfl_down_sync(0xffffffffu, sW, off);
                sC += __shfl_down_sync(0xffffffffu, sC, off);
            }
            if (lane == 0) { wsum[0][warp] = sW; wsum[1][warp] = sC; }
        }
        __syncthreads();
        if (tid == 0 && out_size > NOUT) {
            float mW = 0.f, mC = 0.f;
            for (int e = 0; e < NE; e++) { mW += wsum[0][e]; mC += wsum[1][e]; }
            mW /= NE; mC /= NE;
            float vW = 0.f, vC = 0.f;
            for (int e = 0; e < NE; e++) {
                vW += (wsum[0][e] - mW) * (wsum[0][e] - mW);
                vC += (wsum[1][e] - mC) * (wsum[1][e] - mC);
            }
            vW /= (NE - 1); vC /= (NE - 1);
            out[NOUT] = vW / (mW * mW + 1e-10f) + vC / (mC * mC + 1e-10f);
        }
    }
}

// ---------------- kernel 4b: weight prep (fp16, transpose to [n][k]) --------
#define W1ELEM (NE * NHF * NCH)
__global__ void k_prep(const float* __restrict__ fc1w, const float* __restrict__ fc2w) {
    int idx = blockIdx.x * 256 + threadIdx.x;
    if (idx < W1ELEM) {
        int e = idx >> 16, rem = idx & 65535;
        int n = rem >> 7, k = rem & 127;
        g_w1t[idx] = __float2half_rn(fc1w[((size_t)e * NCH + k) * NHF + n]);
    } else {
        int j = idx - W1ELEM;
        if (j < W1ELEM) {
            int e = j >> 16, rem = j & 65535;
            int jc = rem >> 13, r2 = rem & 8191;
            int c = r2 >> 6, k = r2 & 63;
            g_w2t[j] = __float2half_rn(fc2w[((size_t)e * NHF + jc * 64 + k) * NCH + c]);
        }
    }
}

// ---------------- kernel 5: single-pass fp16 mma MoE (ldmatrix, no-spill) ----
// SMEM map (bytes):
#define S2_X     0                     // [128][136] half = 34816
#define S2_W1    34816                 // 2 buffers x [64][136] half = 2*17408
#define S2_W2    69632                 // [128][72] half = 18432
#define S2_H     88064                 // [128][72] half = 18432
#define S2_SLOT  106496
#define S2_GATE  107008
#define S2_BYTES 107520

__global__ void __launch_bounds__(256, 2)
k_moe(const float* __restrict__ fc1b, const float* __restrict__ fc2b) {
    int e    = blockIdx.x >> 9;
    int tile = blockIdx.x & 511;
    int cnt  = g_cnt[e];
    int row0 = tile << 7;
    if (row0 >= cnt) return;

    extern __shared__ char sm[];
    unsigned sb = smem_u32(sm);
    __half* Xs = (__half*)(sm + S2_X);
    __half* Hs = (__half*)(sm + S2_H);
    int*   slot_s = (int*)(sm + S2_SLOT);
    float* gate_s = (float*)(sm + S2_GATE);

    int tid = threadIdx.x;
    int wid = tid >> 5, lt = tid & 31;
    int qr = lt >> 2, qc = lt & 3;
    int m0 = wid * 16;
    int lrow = lt & 15;
    int lcol = (lt & 16) >> 1;        // 0 or 8 (halfs)

    const __half* w1g = g_w1t + (size_t)e * NHF * NCH;
    const __half* w2g = g_w2t + (size_t)e * NHF * NCH;

    // prefetch W1 chunk 0 into buffer 0
    {
        unsigned d = sb + S2_W1;
#pragma unroll
        for (int it = 0; it < 4; it++) {
            int u = tid + it * 256;              // 0..1023
            int n1 = u >> 4, k16 = u & 15;
            CP16(d + (unsigned)(n1 * 136 + k16 * 8) * 2, w1g + n1 * NCH + k16 * 8);
        }
        CP_COMMIT();
    }

    if (tid < 128) {
        int r = row0 + tid;
        if (r < cnt) { slot_s[tid] = g_list[e * LCAP + r]; gate_s[tid] = g_gate[e * LCAP + r]; }
        else         { slot_s[tid] = -1; gate_s[tid] = 0.f; }
    }
    __syncthreads();

    // gather X -> fp16
#pragma unroll
    for (int it = 0; it < 8; it++) {
        int idx = tid + it * 256;
        int r = idx >> 4, c8 = idx & 15;
        float v[8];
        int s = slot_s[r];
        if (s >= 0) {
            const float4* src = (const float4*)(g_xf + (size_t)(s >> 1) * NCH + c8 * 8);
            float4 a = src[0], b = src[1];
            v[0]=a.x; v[1]=a.y; v[2]=a.z; v[3]=a.w; v[4]=b.x; v[5]=b.y; v[6]=b.z; v[7]=b.w;
        } else {
#pragma unroll
            for (int q = 0; q < 8; q++) v[q] = 0.f;
        }
        uint4 U;
        U.x = pack2h(v[0], v[1]);
        U.y = pack2h(v[2], v[3]);
        U.z = pack2h(v[4], v[5]);
        U.w = pack2h(v[6], v[7]);
        *(uint4*)(Xs + r * 136 + c8 * 8) = U;
    }

    float acc2[16][4];
#pragma unroll
    for (int j = 0; j < 16; j++)
#pragma unroll
        for (int q = 0; q < 4; q++) acc2[j][q] = 0.f;

    // per-lane ldmatrix base addresses (bytes)
    unsigned aX  = sb + S2_X  + (unsigned)((m0 + lrow) * 136 + lcol) * 2;
    unsigned aH  = sb + S2_H  + (unsigned)((m0 + lrow) * 72  + lcol) * 2;
    unsigned bW2 = sb + S2_W2 + (unsigned)(lrow * 72 + lcol) * 2;

    for (int jc = 0; jc < 8; jc++) {
        int cur = jc & 1;
        unsigned bW1 = sb + S2_W1 + cur * 17408 + (unsigned)(lrow * 136 + lcol) * 2;

        // issue W2(jc) async
        {
            unsigned d2 = sb + S2_W2;
            const __half* s2 = w2g + jc * 8192;
#pragma unroll
            for (int it = 0; it < 4; it++) {
                int u = tid + it * 256;
                int n2 = u >> 3, k8 = u & 7;
                CP16(d2 + (unsigned)(n2 * 72 + k8 * 8) * 2, s2 + n2 * 64 + k8 * 8);
            }
            CP_COMMIT();
        }
        CP_WAIT(1);              // W1(jc) arrived
        __syncthreads();

        // GEMM1: [128 x 64] = X * W1^T  -- split into two n-halves
        //        (acc1 = 16 regs, gelu+store per half => no register spills)
#pragma unroll
        for (int half = 0; half < 2; half++) {
            float acc1[4][4];
#pragma unroll
            for (int j = 0; j < 4; j++)
#pragma unroll
                for (int q = 0; q < 4; q++) acc1[j][q] = 0.f;

#pragma unroll
            for (int kt = 0; kt < 8; kt++) {
                unsigned a[4];
                ldm_x4(a, aX + kt * 32);
#pragma unroll
                for (int j2 = 0; j2 < 2; j2++) {
                    unsigned r[4];
                    ldm_x4(r, bW1 + (unsigned)((half * 2 + j2) * 16 * 136) * 2 + kt * 32);
                    unsigned b0[2] = { r[0], r[2] };
                    unsigned b1[2] = { r[1], r[3] };
                    mma16816h(acc1[2 * j2],     a, b0);
                    mma16816h(acc1[2 * j2 + 1], a, b1);
                }
            }
            // bias + gelu -> H for this half (n-tiles half*4 .. half*4+3)
#pragma unroll
            for (int j = 0; j < 4; j++) {
                int n = (half * 4 + j) * 8 + qc * 2;
                float2 b1v = *(const float2*)(fc1b + e * NHF + jc * 64 + n);
                *(unsigned*)(Hs + (m0 + qr) * 72 + n) =
                    pack2h(gelu_exact(acc1[j][0] + b1v.x), gelu_exact(acc1[j][1] + b1v.y));
                *(unsigned*)(Hs + (m0 + qr + 8) * 72 + n) =
                    pack2h(gelu_exact(acc1[j][2] + b1v.x), gelu_exact(acc1[j][3] + b1v.y));
            }
        }
        CP_WAIT(0);              // W2(jc) arrived
        __syncthreads();         // H visible + W2 visible

        // prefetch W1(jc+1) during GEMM2
        if (jc < 7) {
            unsigned d = sb + S2_W1 + (1 - cur) * 17408;
            const __half* s1 = w1g + (jc + 1) * 64 * NCH;
#pragma unroll
            for (int it = 0; it < 4; it++) {
                int u = tid + it * 256;
                int n1 = u >> 4, k16 = u & 15;
                CP16(d + (unsigned)(n1 * 136 + k16 * 8) * 2, s1 + n1 * NCH + k16 * 8);
            }
            CP_COMMIT();
        }

        // GEMM2: [128 x 128] += H * W2^T  (ldmatrix fragments)
#pragma unroll
        for (int kt = 0; kt < 4; kt++) {
            unsigned a[4];
            ldm_x4(a, aH + kt * 32);
#pragma unroll
            for (int j2 = 0; j2 < 8; j2++) {
                unsigned r[4];
                ldm_x4(r, bW2 + (unsigned)(j2 * 16 * 72) * 2 + kt * 32);
                unsigned b0[2] = { r[0], r[2] };
                unsigned b1[2] = { r[1], r[3] };
                mma16816h(acc2[2 * j2],     a, b0);
                mma16816h(acc2[2 * j2 + 1], a, b1);
            }
        }
        __syncthreads();         // protect H + W2 for next chunk
    }

    // epilogue: gate * exp(out + b2) -> g_res
    int mA = m0 + qr, mB = m0 + qr + 8;
    int sA = slot_s[mA], sB = slot_s[mB];
    float gA = gate_s[mA], gB = gate_s[mB];
#pragma unroll
    for (int j = 0; j < 16; j++) {
        int c = j * 8 + qc * 2;
        float2 b2 = *(const float2*)(fc2b + e * NCH + c);
        if (sA >= 0) {
            float2 o;
            o.x = gA * expf(acc2[j][0] + b2.x);
            o.y = gA * expf(acc2[j][1] + b2.y);
            *(float2*)(g_res + (size_t)sA * NCH + c) = o;
        }
        if (sB >= 0) {
            float2 o;
            o.x = gB * expf(acc2[j][2] + b2.x);
            o.y = gB * expf(acc2[j][3] + b2.y);
            *(float2*)(g_res + (size_t)sB * NCH + c) = o;
        }
    }
}

// ---------------- kernel 6: combine + log + transpose back ----------------
__global__ void k_out(float* __restrict__ out) {
    __shared__ float tile[32][33];
    int bh = blockIdx.z;
    int b = bh / NH, h = bh % NH;
    int c0 = blockIdx.x * 32, w0 = blockIdx.y * 32;
    int tx = threadIdx.x, ty = threadIdx.y;
    for (int i = ty; i < 32; i += 8) {
        size_t base = (size_t)(b * NHW + h * NW + w0 + i) * 2 * NCH;
        float v = g_res[base + c0 + tx] + g_res[base + NCH + c0 + tx];
        if (v == 0.f) v = 2.2204460492503131e-16f;
        tile[i][tx] = logf(v);
    }
    __syncthreads();
    for (int i = ty; i < 32; i += 8)
        out[(((size_t)b * NCH + c0 + i) * NH + h) * NW + w0 + tx] = tile[tx][i];
}

// ---------------- launch ----------------
extern "C" void kernel_launch(void* const* d_in, const int* in_sizes, int n_in,
                              void* d_out, int out_size) {
    (void)in_sizes; (void)n_in;
    const float* x       = (const float*)d_in[0];
    const float* prompt  = (const float*)d_in[1];
    const float* de_cls  = (const float*)d_in[2];
    const float* w_g     = (const float*)d_in[3];
    const float* gboost  = (const float*)d_in[4];
    const float* degra_w = (const float*)d_in[5];
    const float* degra_b = (const float*)d_in[6];
    const float* fc1w    = (const float*)d_in[7];
    const float* fc1b    = (const float*)d_in[8];
    const float* fc2w    = (const float*)d_in[9];
    const float* fc2b    = (const float*)d_in[10];
    float* out = (float*)d_out;

    k_init<<<1, 32>>>(prompt, de_cls, w_g, gboost, degra_w, degra_b);
    k_gate<<<GBLK, 256>>>(x, w_g, out, out_size);

    dim3 tb(32, 8);
    k_trans<<<dim3(NCH / 32, NW / 32, NB * NH), tb>>>(x);
    k_prep<<<3072, 256>>>(fc1w, fc2w);

    cudaFuncSetAttribute(k_moe, cudaFuncAttributeMaxDynamicSharedMemorySize, S2_BYTES);
    k_moe<<<NE * 512, 256, S2_BYTES>>>(fc1b, fc2b);

    k_out<<<dim3(NCH / 32, NW / 32, NB * NH), tb>>>(out);
}

// round 9
// speedup vs baseline: 3.5632x; 1.0478x over previous
#include <cuda_runtime.h>
#include <cuda_bf16.h>
#include <cuda_fp16.h>
#include <math.h>

// ---------------- problem constants ----------------
#define NB   2
#define NCH  128
#define NH   128
#define NW   128
#define NE   6
#define ND   6
#define NHF  512
#define NHW  (NH*NW)        // 16384
#define NTOK (NB*NH*NW)     // 32768
#define NOUT (NTOK*NCH)
#define GBLK 128            // gate blocks (256 tokens each)
#define LCAP (2*NTOK)       // per-expert list capacity

// ---------------- scratch ----------------
__device__ float g_xf[NTOK * NCH];
__device__ float g_res[NTOK * 2 * NCH];
__device__ int   g_list[NE * LCAP];
__device__ float g_gate[NE * LCAP];
__device__ int   g_cnt[NE];
__device__ float g_partW[GBLK * NE];
__device__ float g_partC[GBLK * NE];
__device__ unsigned g_done;

// fp16 weights, B layout [n][k]
__device__ __align__(16) __half g_w1t[NE * NHF * NCH];
__device__ __align__(16) __half g_w2t[NE * NHF * NCH];

__device__ __forceinline__ float gelu_exact(float z) {
    return 0.5f * z * (1.0f + erff(z * 0.7071067811865475f));
}
__device__ __forceinline__ unsigned pack2h(float a0, float a1) {
    __half2 h = __floats2half2_rn(a0, a1);
    return *(unsigned*)&h;
}
__device__ __forceinline__ void mma16816h(float* c, const unsigned* a, const unsigned* b) {
    asm volatile("mma.sync.aligned.m16n8k16.row.col.f32.f16.f16.f32 "
                 "{%0,%1,%2,%3}, {%4,%5,%6,%7}, {%8,%9}, {%0,%1,%2,%3};"
                 : "+f"(c[0]), "+f"(c[1]), "+f"(c[2]), "+f"(c[3])
                 : "r"(a[0]), "r"(a[1]), "r"(a[2]), "r"(a[3]),
                   "r"(b[0]), "r"(b[1]));
}
__device__ __forceinline__ void ldm_x4(unsigned* r, unsigned addr) {
    asm volatile("ldmatrix.sync.aligned.m8n8.x4.shared.b16 {%0,%1,%2,%3}, [%4];"
                 : "=r"(r[0]), "=r"(r[1]), "=r"(r[2]), "=r"(r[3]) : "r"(addr));
}
__device__ __forceinline__ unsigned smem_u32(const void* p) {
    unsigned a;
    asm("{ .reg .u64 t; cvta.to.shared.u64 t, %1; cvt.u32.u64 %0, t; }" : "=r"(a) : "l"(p));
    return a;
}
#define CP16(dst, src) \
    asm volatile("cp.async.cg.shared.global [%0], [%1], 16;" :: "r"(dst), "l"(src))
#define CP_COMMIT() asm volatile("cp.async.commit_group;" ::: "memory")
#define CP_WAIT(n)  asm volatile("cp.async.wait_group %0;" :: "n"(n) : "memory")

// ---------------- kernel 1: zero counters only ----------------
__global__ void k_init() {
    int t = threadIdx.x;
    if (t < NE) g_cnt[t] = 0;
    if (t == 31) g_done = 0;
}

// ---------------- kernel 2: gating (coalesced from x, in-block bias) --------
__global__ void __launch_bounds__(256)
k_gate(const float* __restrict__ x, const float* __restrict__ prompt,
       const float* __restrict__ de_cls, const float* __restrict__ w_g,
       const float* __restrict__ gboost, const float* __restrict__ degra_w,
       const float* __restrict__ degra_b,
       float* __restrict__ out, int out_size) {
    __shared__ float wg_s[NCH * NE];
    __shared__ float bias_s[NE];
    __shared__ float wsum[8][NE];
    __shared__ int   wcnt[8][NE];
    __shared__ unsigned is_last_s;
    int tid = threadIdx.x;
    int warp = tid >> 5, lane = tid & 31;
    int n = blockIdx.x * 256 + tid;
    int b = n >> 14;                  // whole block shares one b (16384 % 256 == 0)

    for (int i = tid; i < NCH * NE; i += 256) wg_s[i] = w_g[i];

    // warps 0..5: compute bias for expert e = warp
    if (warp < NE) {
        int e = warp;
        float s1 = 0.f;
#pragma unroll
        for (int q = 0; q < 4; q++) {
            int c = lane + q * 32;
            s1 += prompt[b * NCH + c] * w_g[(NCH + c) * NE + e];
        }
        float s2 = (lane < ND) ? de_cls[b * ND + lane] * degra_w[lane * NE + e] : 0.f;
        for (int off = 16; off; off >>= 1) {
            s1 += __shfl_down_sync(0xffffffffu, s1, off);
            s2 += __shfl_down_sync(0xffffffffu, s2, off);
        }
        if (lane == 0) bias_s[e] = s1 + gboost[0] * (s2 + degra_b[e]);
    }
    __syncthreads();

    int hw = n & (NHW - 1);
    float acc[NE];
#pragma unroll
    for (int e = 0; e < NE; e++) acc[e] = bias_s[e];
    const float* xb = x + (size_t)b * NCH * NHW + hw;
#pragma unroll 4
    for (int c = 0; c < NCH; c++) {
        float xv = xb[(size_t)c * NHW];
#pragma unroll
        for (int e = 0; e < NE; e++) acc[e] += xv * wg_s[c * NE + e];
    }
    int i0 = 0; float v0 = acc[0];
#pragma unroll
    for (int e = 1; e < NE; e++) if (acc[e] > v0) { v0 = acc[e]; i0 = e; }
    int i1 = (i0 == 0) ? 1 : 0; float v1 = acc[i1];
#pragma unroll
    for (int e = 0; e < NE; e++)
        if (e != i0 && acc[e] > v1) { v1 = acc[e]; i1 = e; }
    float g0 = 1.f / (1.f + expf(v1 - v0));
    float g1 = 1.f - g0;

    int p0 = atomicAdd(&g_cnt[i0], 1);
    g_list[i0 * LCAP + p0] = n * 2 + 0;
    g_gate[i0 * LCAP + p0] = g0;
    int p1 = atomicAdd(&g_cnt[i1], 1);
    g_list[i1 * LCAP + p1] = n * 2 + 1;
    g_gate[i1 * LCAP + p1] = g1;

#pragma unroll
    for (int e = 0; e < NE; e++) {
        float gv = (i0 == e ? g0 : 0.f) + (i1 == e ? g1 : 0.f);
        int   cv = (i0 == e) + (i1 == e);
        for (int off = 16; off; off >>= 1) {
            gv += __shfl_down_sync(0xffffffffu, gv, off);
            cv += __shfl_down_sync(0xffffffffu, cv, off);
        }
        if (lane == 0) { wsum[warp][e] = gv; wcnt[warp][e] = cv; }
    }
    __syncthreads();
    if (tid < NE) {
        float s = 0.f; int c = 0;
#pragma unroll
        for (int w = 0; w < 8; w++) { s += wsum[w][tid]; c += wcnt[w][tid]; }
        g_partW[blockIdx.x * NE + tid] = s;
        g_partC[blockIdx.x * NE + tid] = (float)c;
    }
    __threadfence();
    __syncthreads();
    if (tid == 0) is_last_s = (atomicAdd(&g_done, 1u) == GBLK - 1);
    __syncthreads();
    if (is_last_s) {
        if (warp < NE) {
            float sW = g_partW[lane * NE + warp] + g_partW[(lane + 32) * NE + warp]
                     + g_partW[(lane + 64) * NE + warp] + g_partW[(lane + 96) * NE + warp];
            float sC = g_partC[lane * NE + warp] + g_partC[(lane + 32) * NE + warp]
                     + g_partC[(lane + 64) * NE + warp] + g_partC[(lane + 96) * NE + warp];
            for (int off = 16; off; off >>= 1) {
                sW += __shfl_down_sync(0xffffffffu, sW, off);
                sC += __shfl_down_sync(0xffffffffu, sC, off);
            }
            if (lane == 0) { wsum[0][warp] = sW; wsum[1][warp] = sC; }
        }
        __syncthreads();
        if (tid == 0 && out_size > NOUT) {
            float mW = 0.f, mC = 0.f;
            for (int e = 0; e < NE; e++) { mW += wsum[0][e]; mC += wsum[1][e]; }
            mW /= NE; mC /= NE;
            float vW = 0.f, vC = 0.f;
            for (int e = 0; e < NE; e++) {
                vW += (wsum[0][e] - mW) * (wsum[0][e] - mW);
                vC += (wsum[1][e] - mC) * (wsum[1][e] - mC);
            }
            vW /= (NE - 1); vC /= (NE - 1);
            out[NOUT] = vW / (mW * mW + 1e-10f) + vC / (mC * mC + 1e-10f);
        }
    }
}

// ---------------- kernel 3: fused transpose + weight prep --------------------
#define TPBLK 4096                     // transpose blocks; prep blocks follow
#define W1ELEM (NE * NHF * NCH)
__global__ void __launch_bounds__(256)
k_tp(const float* __restrict__ x,
     const float* __restrict__ fc1w, const float* __restrict__ fc2w) {
    __shared__ float tile[32][33];
    int bid = blockIdx.x;
    int tid = threadIdx.x;
    if (bid < TPBLK) {
        int cx = bid & 3, wy = (bid >> 2) & 3, bh = bid >> 4;
        int b = bh / NH, h = bh % NH;
        int c0 = cx * 32, w0 = wy * 32;
        int tx = tid & 31, ty = tid >> 5;
        for (int i = ty; i < 32; i += 8)
            tile[i][tx] = x[(((size_t)b * NCH + c0 + i) * NH + h) * NW + w0 + tx];
        __syncthreads();
        for (int i = ty; i < 32; i += 8)
            g_xf[((size_t)(b * NHW + h * NW + w0 + i)) * NCH + c0 + tx] = tile[tx][i];
    } else {
        int idx = (bid - TPBLK) * 256 + tid;
        if (idx < W1ELEM) {
            int e = idx >> 16, rem = idx & 65535;
            int n = rem >> 7, k = rem & 127;
            g_w1t[idx] = __float2half_rn(fc1w[((size_t)e * NCH + k) * NHF + n]);
        } else {
            int j = idx - W1ELEM;
            if (j < W1ELEM) {
                int e = j >> 16, rem = j & 65535;
                int jc = rem >> 13, r2 = rem & 8191;
                int c = r2 >> 6, k = r2 & 63;
                g_w2t[j] = __float2half_rn(fc2w[((size_t)e * NHF + jc * 64 + k) * NCH + c]);
            }
        }
    }
}

// ---------------- kernel 4: single-pass fp16 mma MoE (ldmatrix) --------------
// SMEM map (bytes):
#define S2_X     0                     // [128][136] half = 34816
#define S2_W1    34816                 // 2 buffers x [64][136] half = 2*17408
#define S2_W2    69632                 // [128][72] half = 18432
#define S2_H     88064                 // [128][72] half = 18432
#define S2_SLOT  106496
#define S2_GATE  107008
#define S2_BYTES 107520

__global__ void __launch_bounds__(256, 2)
k_moe(const float* __restrict__ fc1b, const float* __restrict__ fc2b) {
    int e    = blockIdx.x >> 9;
    int tile = blockIdx.x & 511;
    int cnt  = g_cnt[e];
    int row0 = tile << 7;
    if (row0 >= cnt) return;

    extern __shared__ char sm[];
    unsigned sb = smem_u32(sm);
    __half* Xs = (__half*)(sm + S2_X);
    __half* Hs = (__half*)(sm + S2_H);
    int*   slot_s = (int*)(sm + S2_SLOT);
    float* gate_s = (float*)(sm + S2_GATE);

    int tid = threadIdx.x;
    int wid = tid >> 5, lt = tid & 31;
    int qr = lt >> 2, qc = lt & 3;
    int m0 = wid * 16;
    int lrow = lt & 15;
    int lcol = (lt & 16) >> 1;        // 0 or 8 (halfs)

    const __half* w1g = g_w1t + (size_t)e * NHF * NCH;
    const __half* w2g = g_w2t + (size_t)e * NHF * NCH;

    // prefetch W1 chunk 0 into buffer 0
    {
        unsigned d = sb + S2_W1;
#pragma unroll
        for (int it = 0; it < 4; it++) {
            int u = tid + it * 256;              // 0..1023
            int n1 = u >> 4, k16 = u & 15;
            CP16(d + (unsigned)(n1 * 136 + k16 * 8) * 2, w1g + n1 * NCH + k16 * 8);
        }
        CP_COMMIT();
    }

    if (tid < 128) {
        int r = row0 + tid;
        if (r < cnt) { slot_s[tid] = g_list[e * LCAP + r]; gate_s[tid] = g_gate[e * LCAP + r]; }
        else         { slot_s[tid] = -1; gate_s[tid] = 0.f; }
    }
    __syncthreads();

    // gather X -> fp16
#pragma unroll
    for (int it = 0; it < 8; it++) {
        int idx = tid + it * 256;
        int r = idx >> 4, c8 = idx & 15;
        float v[8];
        int s = slot_s[r];
        if (s >= 0) {
            const float4* src = (const float4*)(g_xf + (size_t)(s >> 1) * NCH + c8 * 8);
            float4 a = src[0], b = src[1];
            v[0]=a.x; v[1]=a.y; v[2]=a.z; v[3]=a.w; v[4]=b.x; v[5]=b.y; v[6]=b.z; v[7]=b.w;
        } else {
#pragma unroll
            for (int q = 0; q < 8; q++) v[q] = 0.f;
        }
        uint4 U;
        U.x = pack2h(v[0], v[1]);
        U.y = pack2h(v[2], v[3]);
        U.z = pack2h(v[4], v[5]);
        U.w = pack2h(v[6], v[7]);
        *(uint4*)(Xs + r * 136 + c8 * 8) = U;
    }

    float acc2[16][4];
#pragma unroll
    for (int j = 0; j < 16; j++)
#pragma unroll
        for (int q = 0; q < 4; q++) acc2[j][q] = 0.f;

    // per-lane ldmatrix base addresses (bytes)
    unsigned aX  = sb + S2_X  + (unsigned)((m0 + lrow) * 136 + lcol) * 2;
    unsigned aH  = sb + S2_H  + (unsigned)((m0 + lrow) * 72  + lcol) * 2;
    unsigned bW2 = sb + S2_W2 + (unsigned)(lrow * 72 + lcol) * 2;

    for (int jc = 0; jc < 8; jc++) {
        int cur = jc & 1;
        unsigned bW1 = sb + S2_W1 + cur * 17408 + (unsigned)(lrow * 136 + lcol) * 2;

        // issue W2(jc) async
        {
            unsigned d2 = sb + S2_W2;
            const __half* s2 = w2g + jc * 8192;
#pragma unroll
            for (int it = 0; it < 4; it++) {
                int u = tid + it * 256;
                int n2 = u >> 3, k8 = u & 7;
                CP16(d2 + (unsigned)(n2 * 72 + k8 * 8) * 2, s2 + n2 * 64 + k8 * 8);
            }
            CP_COMMIT();
        }
        CP_WAIT(1);              // W1(jc) arrived
        __syncthreads();

        // GEMM1: [128 x 64] = X * W1^T  -- two n-halves (low reg pressure)
#pragma unroll
        for (int half = 0; half < 2; half++) {
            float acc1[4][4];
#pragma unroll
            for (int j = 0; j < 4; j++)
#pragma unroll
                for (int q = 0; q < 4; q++) acc1[j][q] = 0.f;

#pragma unroll
            for (int kt = 0; kt < 8; kt++) {
                unsigned a[4];
                ldm_x4(a, aX + kt * 32);
#pragma unroll
                for (int j2 = 0; j2 < 2; j2++) {
                    unsigned r[4];
                    ldm_x4(r, bW1 + (unsigned)((half * 2 + j2) * 16 * 136) * 2 + kt * 32);
                    unsigned b0[2] = { r[0], r[2] };
                    unsigned b1[2] = { r[1], r[3] };
                    mma16816h(acc1[2 * j2],     a, b0);
                    mma16816h(acc1[2 * j2 + 1], a, b1);
                }
            }
#pragma unroll
            for (int j = 0; j < 4; j++) {
                int n = (half * 4 + j) * 8 + qc * 2;
                float2 b1v = *(const float2*)(fc1b + e * NHF + jc * 64 + n);
                *(unsigned*)(Hs + (m0 + qr) * 72 + n) =
                    pack2h(gelu_exact(acc1[j][0] + b1v.x), gelu_exact(acc1[j][1] + b1v.y));
                *(unsigned*)(Hs + (m0 + qr + 8) * 72 + n) =
                    pack2h(gelu_exact(acc1[j][2] + b1v.x), gelu_exact(acc1[j][3] + b1v.y));
            }
        }
        CP_WAIT(0);              // W2(jc) arrived
        __syncthreads();         // H visible + W2 visible

        // prefetch W1(jc+1) during GEMM2
        if (jc < 7) {
            unsigned d = sb + S2_W1 + (1 - cur) * 17408;
            const __half* s1 = w1g + (jc + 1) * 64 * NCH;
#pragma unroll
            for (int it = 0; it < 4; it++) {
                int u = tid + it * 256;
                int n1 = u >> 4, k16 = u & 15;
                CP16(d + (unsigned)(n1 * 136 + k16 * 8) * 2, s1 + n1 * NCH + k16 * 8);
            }
            CP_COMMIT();
        }

        // GEMM2: [128 x 128] += H * W2^T
#pragma unroll
        for (int kt = 0; kt < 4; kt++) {
            unsigned a[4];
            ldm_x4(a, aH + kt * 32);
#pragma unroll
            for (int j2 = 0; j2 < 8; j2++) {
                unsigned r[4];
                ldm_x4(r, bW2 + (unsigned)(j2 * 16 * 72) * 2 + kt * 32);
                unsigned b0[2] = { r[0], r[2] };
                unsigned b1[2] = { r[1], r[3] };
                mma16816h(acc2[2 * j2],     a, b0);
                mma16816h(acc2[2 * j2 + 1], a, b1);
            }
        }
        __syncthreads();         // protect H + W2 for next chunk
    }

    // epilogue: gate * exp(out + b2) -> g_res
    int mA = m0 + qr, mB = m0 + qr + 8;
    int sA = slot_s[mA], sB = slot_s[mB];
    float gA = gate_s[mA], gB = gate_s[mB];
#pragma unroll
    for (int j = 0; j < 16; j++) {
        int c = j * 8 + qc * 2;
        float2 b2 = *(const float2*)(fc2b + e * NCH + c);
        if (sA >= 0) {
            float2 o;
            o.x = gA * expf(acc2[j][0] + b2.x);
            o.y = gA * expf(acc2[j][1] + b2.y);
            *(float2*)(g_res + (size_t)sA * NCH + c) = o;
        }
        if (sB >= 0) {
            float2 o;
            o.x = gB * expf(acc2[j][2] + b2.x);
            o.y = gB * expf(acc2[j][3] + b2.y);
            *(float2*)(g_res + (size_t)sB * NCH + c) = o;
        }
    }
}

// ---------------- kernel 5: combine + log + transpose back ----------------
__global__ void k_out(float* __restrict__ out) {
    __shared__ float tile[32][33];
    int bh = blockIdx.z;
    int b = bh / NH, h = bh % NH;
    int c0 = blockIdx.x * 32, w0 = blockIdx.y * 32;
    int tx = threadIdx.x, ty = threadIdx.y;
    for (int i = ty; i < 32; i += 8) {
        size_t base = (size_t)(b * NHW + h * NW + w0 + i) * 2 * NCH;
        float v = g_res[base + c0 + tx] + g_res[base + NCH + c0 + tx];
        if (v == 0.f) v = 2.2204460492503131e-16f;
        tile[i][tx] = logf(v);
    }
    __syncthreads();
    for (int i = ty; i < 32; i += 8)
        out[(((size_t)b * NCH + c0 + i) * NH + h) * NW + w0 + tx] = tile[tx][i];
}

// ---------------- launch ----------------
extern "C" void kernel_launch(void* const* d_in, const int* in_sizes, int n_in,
                              void* d_out, int out_size) {
    (void)in_sizes; (void)n_in;
    const float* x       = (const float*)d_in[0];
    const float* prompt  = (const float*)d_in[1];
    const float* de_cls  = (const float*)d_in[2];
    const float* w_g     = (const float*)d_in[3];
    const float* gboost  = (const float*)d_in[4];
    const float* degra_w = (const float*)d_in[5];
    const float* degra_b = (const float*)d_in[6];
    const float* fc1w    = (const float*)d_in[7];
    const float* fc1b    = (const float*)d_in[8];
    const float* fc2w    = (const float*)d_in[9];
    const float* fc2b    = (const float*)d_in[10];
    float* out = (float*)d_out;

    k_init<<<1, 32>>>();
    k_gate<<<GBLK, 256>>>(x, prompt, de_cls, w_g, gboost, degra_w, degra_b,
                          out, out_size);
    k_tp<<<TPBLK + 3072, 256>>>(x, fc1w, fc2w);

    cudaFuncSetAttribute(k_moe, cudaFuncAttributeMaxDynamicSharedMemorySize, S2_BYTES);
    k_moe<<<NE * 512, 256, S2_BYTES>>>(fc1b, fc2b);

    k_out<<<dim3(NCH / 32, NW / 32, NB * NH), dim3(32, 8)>>>(out);
}

// round 10
// speedup vs baseline: 3.6464x; 1.0233x over previous
#include <cuda_runtime.h>
#include <cuda_bf16.h>
#include <cuda_fp16.h>
#include <math.h>

// ---------------- problem constants ----------------
#define NB   2
#define NCH  128
#define NH   128
#define NW   128
#define NE   6
#define ND   6
#define NHF  512
#define NHW  (NH*NW)        // 16384
#define NTOK (NB*NH*NW)     // 32768
#define NOUT (NTOK*NCH)
#define GBLK 128            // gate blocks (256 tokens each)
#define LCAP (2*NTOK)       // per-expert list capacity

// ---------------- scratch ----------------
__device__ float g_xf[NTOK * NCH];
__device__ float g_res[NTOK * 2 * NCH];
__device__ int   g_list[NE * LCAP];
__device__ float g_gate[NE * LCAP];
__device__ int   g_cnt[NE];
__device__ float g_partW[GBLK * NE];
__device__ float g_partC[GBLK * NE];
__device__ unsigned g_done;

// fp16 weights, B layout [n][k]
__device__ __align__(16) __half g_w1t[NE * NHF * NCH];
__device__ __align__(16) __half g_w2t[NE * NHF * NCH];

__device__ __forceinline__ float gelu_exact(float z) {
    return 0.5f * z * (1.0f + erff(z * 0.7071067811865475f));
}
__device__ __forceinline__ unsigned pack2h(float a0, float a1) {
    __half2 h = __floats2half2_rn(a0, a1);
    return *(unsigned*)&h;
}
__device__ __forceinline__ void mma16816h(float* c, const unsigned* a, const unsigned* b) {
    asm volatile("mma.sync.aligned.m16n8k16.row.col.f32.f16.f16.f32 "
                 "{%0,%1,%2,%3}, {%4,%5,%6,%7}, {%8,%9}, {%0,%1,%2,%3};"
                 : "+f"(c[0]), "+f"(c[1]), "+f"(c[2]), "+f"(c[3])
                 : "r"(a[0]), "r"(a[1]), "r"(a[2]), "r"(a[3]),
                   "r"(b[0]), "r"(b[1]));
}
__device__ __forceinline__ void ldm_x4(unsigned* r, unsigned addr) {
    asm volatile("ldmatrix.sync.aligned.m8n8.x4.shared.b16 {%0,%1,%2,%3}, [%4];"
                 : "=r"(r[0]), "=r"(r[1]), "=r"(r[2]), "=r"(r[3]) : "r"(addr));
}
__device__ __forceinline__ unsigned smem_u32(const void* p) {
    unsigned a;
    asm("{ .reg .u64 t; cvta.to.shared.u64 t, %1; cvt.u32.u64 %0, t; }" : "=r"(a) : "l"(p));
    return a;
}
#define CP16(dst, src) \
    asm volatile("cp.async.cg.shared.global [%0], [%1], 16;" :: "r"(dst), "l"(src))
#define CP_COMMIT() asm volatile("cp.async.commit_group;" ::: "memory")
#define CP_WAIT(n)  asm volatile("cp.async.wait_group %0;" :: "n"(n) : "memory")

// ---------------- kernel 1: zero counters only ----------------
__global__ void k_init() {
    int t = threadIdx.x;
    if (t < NE) g_cnt[t] = 0;
    if (t == 31) g_done = 0;
}

// ---------------- kernel 2: gating (coalesced from x, in-block bias) --------
__global__ void __launch_bounds__(256)
k_gate(const float* __restrict__ x, const float* __restrict__ prompt,
       const float* __restrict__ de_cls, const float* __restrict__ w_g,
       const float* __restrict__ gboost, const float* __restrict__ degra_w,
       const float* __restrict__ degra_b,
       float* __restrict__ out, int out_size) {
    __shared__ float wg_s[NCH * NE];
    __shared__ float bias_s[NE];
    __shared__ float wsum[8][NE];
    __shared__ int   wcnt[8][NE];
    __shared__ unsigned is_last_s;
    int tid = threadIdx.x;
    int warp = tid >> 5, lane = tid & 31;
    int n = blockIdx.x * 256 + tid;
    int b = n >> 14;                  // whole block shares one b (16384 % 256 == 0)

    for (int i = tid; i < NCH * NE; i += 256) wg_s[i] = w_g[i];

    if (warp < NE) {
        int e = warp;
        float s1 = 0.f;
#pragma unroll
        for (int q = 0; q < 4; q++) {
            int c = lane + q * 32;
            s1 += prompt[b * NCH + c] * w_g[(NCH + c) * NE + e];
        }
        float s2 = (lane < ND) ? de_cls[b * ND + lane] * degra_w[lane * NE + e] : 0.f;
        for (int off = 16; off; off >>= 1) {
            s1 += __shfl_down_sync(0xffffffffu, s1, off);
            s2 += __shfl_down_sync(0xffffffffu, s2, off);
        }
        if (lane == 0) bias_s[e] = s1 + gboost[0] * (s2 + degra_b[e]);
    }
    __syncthreads();

    int hw = n & (NHW - 1);
    float acc[NE];
#pragma unroll
    for (int e = 0; e < NE; e++) acc[e] = bias_s[e];
    const float* xb = x + (size_t)b * NCH * NHW + hw;
#pragma unroll 4
    for (int c = 0; c < NCH; c++) {
        float xv = xb[(size_t)c * NHW];
#pragma unroll
        for (int e = 0; e < NE; e++) acc[e] += xv * wg_s[c * NE + e];
    }
    int i0 = 0; float v0 = acc[0];
#pragma unroll
    for (int e = 1; e < NE; e++) if (acc[e] > v0) { v0 = acc[e]; i0 = e; }
    int i1 = (i0 == 0) ? 1 : 0; float v1 = acc[i1];
#pragma unroll
    for (int e = 0; e < NE; e++)
        if (e != i0 && acc[e] > v1) { v1 = acc[e]; i1 = e; }
    float g0 = 1.f / (1.f + expf(v1 - v0));
    float g1 = 1.f - g0;

    int p0 = atomicAdd(&g_cnt[i0], 1);
    g_list[i0 * LCAP + p0] = n * 2 + 0;
    g_gate[i0 * LCAP + p0] = g0;
    int p1 = atomicAdd(&g_cnt[i1], 1);
    g_list[i1 * LCAP + p1] = n * 2 + 1;
    g_gate[i1 * LCAP + p1] = g1;

#pragma unroll
    for (int e = 0; e < NE; e++) {
        float gv = (i0 == e ? g0 : 0.f) + (i1 == e ? g1 : 0.f);
        int   cv = (i0 == e) + (i1 == e);
        for (int off = 16; off; off >>= 1) {
            gv += __shfl_down_sync(0xffffffffu, gv, off);
            cv += __shfl_down_sync(0xffffffffu, cv, off);
        }
        if (lane == 0) { wsum[warp][e] = gv; wcnt[warp][e] = cv; }
    }
    __syncthreads();
    if (tid < NE) {
        float s = 0.f; int c = 0;
#pragma unroll
        for (int w = 0; w < 8; w++) { s += wsum[w][tid]; c += wcnt[w][tid]; }
        g_partW[blockIdx.x * NE + tid] = s;
        g_partC[blockIdx.x * NE + tid] = (float)c;
    }
    __threadfence();
    __syncthreads();
    if (tid == 0) is_last_s = (atomicAdd(&g_done, 1u) == GBLK - 1);
    __syncthreads();
    if (is_last_s) {
        if (warp < NE) {
            float sW = g_partW[lane * NE + warp] + g_partW[(lane + 32) * NE + warp]
                     + g_partW[(lane + 64) * NE + warp] + g_partW[(lane + 96) * NE + warp];
            float sC = g_partC[lane * NE + warp] + g_partC[(lane + 32) * NE + warp]
                     + g_partC[(lane + 64) * NE + warp] + g_partC[(lane + 96) * NE + warp];
            for (int off = 16; off; off >>= 1) {
                sW += __shfl_down_sync(0xffffffffu, sW, off);
                sC += __shfl_down_sync(0xffffffffu, sC, off);
            }
            if (lane == 0) { wsum[0][warp] = sW; wsum[1][warp] = sC; }
        }
        __syncthreads();
        if (tid == 0 && out_size > NOUT) {
            float mW = 0.f, mC = 0.f;
            for (int e = 0; e < NE; e++) { mW += wsum[0][e]; mC += wsum[1][e]; }
            mW /= NE; mC /= NE;
            float vW = 0.f, vC = 0.f;
            for (int e = 0; e < NE; e++) {
                vW += (wsum[0][e] - mW) * (wsum[0][e] - mW);
                vC += (wsum[1][e] - mC) * (wsum[1][e] - mC);
            }
            vW /= (NE - 1); vC /= (NE - 1);
            out[NOUT] = vW / (mW * mW + 1e-10f) + vC / (mC * mC + 1e-10f);
        }
    }
}

// ---------------- kernel 3: fused transpose + weight prep --------------------
#define TPBLK 4096
#define W1ELEM (NE * NHF * NCH)
__global__ void __launch_bounds__(256)
k_tp(const float* __restrict__ x,
     const float* __restrict__ fc1w, const float* __restrict__ fc2w) {
    __shared__ float tile[32][33];
    int bid = blockIdx.x;
    int tid = threadIdx.x;
    if (bid < TPBLK) {
        int cx = bid & 3, wy = (bid >> 2) & 3, bh = bid >> 4;
        int b = bh / NH, h = bh % NH;
        int c0 = cx * 32, w0 = wy * 32;
        int tx = tid & 31, ty = tid >> 5;
        for (int i = ty; i < 32; i += 8)
            tile[i][tx] = x[(((size_t)b * NCH + c0 + i) * NH + h) * NW + w0 + tx];
        __syncthreads();
        for (int i = ty; i < 32; i += 8)
            g_xf[((size_t)(b * NHW + h * NW + w0 + i)) * NCH + c0 + tx] = tile[tx][i];
    } else {
        int idx = (bid - TPBLK) * 256 + tid;
        if (idx < W1ELEM) {
            int e = idx >> 16, rem = idx & 65535;
            int n = rem >> 7, k = rem & 127;
            g_w1t[idx] = __float2half_rn(fc1w[((size_t)e * NCH + k) * NHF + n]);
        } else {
            int j = idx - W1ELEM;
            if (j < W1ELEM) {
                int e = j >> 16, rem = j & 65535;
                int jc = rem >> 13, r2 = rem & 8191;
                int c = r2 >> 6, k = r2 & 63;
                g_w2t[j] = __float2half_rn(fc2w[((size_t)e * NHF + jc * 64 + k) * NCH + c]);
            }
        }
    }
}

// ---------------- kernel 4: fp16 mma MoE, m32 warp tiles ---------------------
// SMEM map (bytes):
#define S2_X     0                     // [128][136] half = 34816
#define S2_W1    34816                 // 2 buffers x [64][136] half = 2*17408
#define S2_W2    69632                 // [128][72] half = 18432
#define S2_H     88064                 // [128][72] half = 18432
#define S2_SLOT  106496
#define S2_GATE  107008
#define S2_BYTES 107520

__global__ void __launch_bounds__(256, 2)
k_moe(const float* __restrict__ fc1b, const float* __restrict__ fc2b) {
    int e    = blockIdx.x >> 9;
    int tile = blockIdx.x & 511;
    int cnt  = g_cnt[e];
    int row0 = tile << 7;
    if (row0 >= cnt) return;

    extern __shared__ char sm[];
    unsigned sb = smem_u32(sm);
    __half* Hs = (__half*)(sm + S2_H);
    int*   slot_s = (int*)(sm + S2_SLOT);
    float* gate_s = (float*)(sm + S2_GATE);

    int tid = threadIdx.x;
    int wid = tid >> 5, lt = tid & 31;
    int qr = lt >> 2, qc = lt & 3;
    int mb  = (wid & 3) * 32;          // warp m-block (32 rows)
    int nb1 = (wid >> 2) * 32;         // GEMM1 n-block (32 of 64)
    int nb2 = (wid >> 2) * 64;         // GEMM2 n-block (64 of 128)
    int lrow = lt & 15;
    int lcol = (lt & 16) >> 1;         // 0 or 8 (halfs)

    const __half* w1g = g_w1t + (size_t)e * NHF * NCH;
    const __half* w2g = g_w2t + (size_t)e * NHF * NCH;

    // prefetch W1 chunk 0 into buffer 0
    {
        unsigned d = sb + S2_W1;
#pragma unroll
        for (int it = 0; it < 4; it++) {
            int u = tid + it * 256;              // 0..1023
            int n1 = u >> 4, k16 = u & 15;
            CP16(d + (unsigned)(n1 * 136 + k16 * 8) * 2, w1g + n1 * NCH + k16 * 8);
        }
        CP_COMMIT();
    }

    if (tid < 128) {
        int r = row0 + tid;
        if (r < cnt) { slot_s[tid] = g_list[e * LCAP + r]; gate_s[tid] = g_gate[e * LCAP + r]; }
        else         { slot_s[tid] = -1; gate_s[tid] = 0.f; }
    }
    __syncthreads();

    // gather X -> fp16
#pragma unroll
    for (int it = 0; it < 8; it++) {
        int idx = tid + it * 256;
        int r = idx >> 4, c8 = idx & 15;
        float v[8];
        int s = slot_s[r];
        if (s >= 0) {
            const float4* src = (const float4*)(g_xf + (size_t)(s >> 1) * NCH + c8 * 8);
            float4 a = src[0], b = src[1];
            v[0]=a.x; v[1]=a.y; v[2]=a.z; v[3]=a.w; v[4]=b.x; v[5]=b.y; v[6]=b.z; v[7]=b.w;
        } else {
#pragma unroll
            for (int q = 0; q < 8; q++) v[q] = 0.f;
        }
        uint4 U;
        U.x = pack2h(v[0], v[1]);
        U.y = pack2h(v[2], v[3]);
        U.z = pack2h(v[4], v[5]);
        U.w = pack2h(v[6], v[7]);
        *(uint4*)((__half*)(sm + S2_X) + r * 136 + c8 * 8) = U;
    }

    float acc2[2][8][4];
#pragma unroll
    for (int i = 0; i < 2; i++)
#pragma unroll
        for (int j = 0; j < 8; j++)
#pragma unroll
            for (int q = 0; q < 4; q++) acc2[i][j][q] = 0.f;

    // per-lane ldmatrix base addresses (bytes)
    unsigned aX  = sb + S2_X  + (unsigned)((mb + lrow) * 136 + lcol) * 2;
    unsigned aH  = sb + S2_H  + (unsigned)((mb + lrow) * 72  + lcol) * 2;
    unsigned bW2 = sb + S2_W2 + (unsigned)((nb2 + lrow) * 72 + lcol) * 2;

    for (int jc = 0; jc < 8; jc++) {
        int cur = jc & 1;
        unsigned bW1 = sb + S2_W1 + cur * 17408 + (unsigned)((nb1 + lrow) * 136 + lcol) * 2;

        // issue W2(jc) async
        {
            unsigned d2 = sb + S2_W2;
            const __half* s2 = w2g + jc * 8192;
#pragma unroll
            for (int it = 0; it < 4; it++) {
                int u = tid + it * 256;
                int n2 = u >> 3, k8 = u & 7;
                CP16(d2 + (unsigned)(n2 * 72 + k8 * 8) * 2, s2 + n2 * 64 + k8 * 8);
            }
            CP_COMMIT();
        }
        CP_WAIT(1);              // W1(jc) arrived
        __syncthreads();

        // GEMM1: warp tile m32 x n32, A reused across both n16 groups
        float acc1[2][4][4];
#pragma unroll
        for (int i = 0; i < 2; i++)
#pragma unroll
            for (int j = 0; j < 4; j++)
#pragma unroll
                for (int q = 0; q < 4; q++) acc1[i][j][q] = 0.f;

#pragma unroll
        for (int kt = 0; kt < 8; kt++) {
            unsigned a0[4], a1[4];
            ldm_x4(a0, aX + kt * 32);
            ldm_x4(a1, aX + 16 * 136 * 2 + kt * 32);
#pragma unroll
            for (int j2 = 0; j2 < 2; j2++) {
                unsigned r[4];
                ldm_x4(r, bW1 + (unsigned)(j2 * 16 * 136) * 2 + kt * 32);
                unsigned b0[2] = { r[0], r[2] };
                unsigned b1[2] = { r[1], r[3] };
                mma16816h(acc1[0][2 * j2],     a0, b0);
                mma16816h(acc1[0][2 * j2 + 1], a0, b1);
                mma16816h(acc1[1][2 * j2],     a1, b0);
                mma16816h(acc1[1][2 * j2 + 1], a1, b1);
            }
        }
        // bias + gelu -> H (warp writes rows mb..mb+31, cols nb1..nb1+31)
#pragma unroll
        for (int i = 0; i < 2; i++)
#pragma unroll
            for (int j = 0; j < 4; j++) {
                int n = nb1 + j * 8 + qc * 2;
                float2 b1v = *(const float2*)(fc1b + e * NHF + jc * 64 + n);
                *(unsigned*)(Hs + (mb + i * 16 + qr) * 72 + n) =
                    pack2h(gelu_exact(acc1[i][j][0] + b1v.x),
                           gelu_exact(acc1[i][j][1] + b1v.y));
                *(unsigned*)(Hs + (mb + i * 16 + qr + 8) * 72 + n) =
                    pack2h(gelu_exact(acc1[i][j][2] + b1v.x),
                           gelu_exact(acc1[i][j][3] + b1v.y));
            }
        CP_WAIT(0);              // W2(jc) arrived
        __syncthreads();         // H visible + W2 visible

        // prefetch W1(jc+1) during GEMM2
        if (jc < 7) {
            unsigned d = sb + S2_W1 + (1 - cur) * 17408;
            const __half* s1 = w1g + (jc + 1) * 64 * NCH;
#pragma unroll
            for (int it = 0; it < 4; it++) {
                int u = tid + it * 256;
                int n1 = u >> 4, k16 = u & 15;
                CP16(d + (unsigned)(n1 * 136 + k16 * 8) * 2, s1 + n1 * NCH + k16 * 8);
            }
            CP_COMMIT();
        }

        // GEMM2: warp tile m32 x n64
#pragma unroll
        for (int kt = 0; kt < 4; kt++) {
            unsigned a0[4], a1[4];
            ldm_x4(a0, aH + kt * 32);
            ldm_x4(a1, aH + 16 * 72 * 2 + kt * 32);
#pragma unroll
            for (int j2 = 0; j2 < 4; j2++) {
                unsigned r[4];
                ldm_x4(r, bW2 + (unsigned)(j2 * 16 * 72) * 2 + kt * 32);
                unsigned b0[2] = { r[0], r[2] };
                unsigned b1[2] = { r[1], r[3] };
                mma16816h(acc2[0][2 * j2],     a0, b0);
                mma16816h(acc2[0][2 * j2 + 1], a0, b1);
                mma16816h(acc2[1][2 * j2],     a1, b0);
                mma16816h(acc2[1][2 * j2 + 1], a1, b1);
            }
        }
        __syncthreads();         // protect H + W2 for next chunk
    }

    // epilogue: gate * exp(out + b2) -> g_res
#pragma unroll
    for (int i = 0; i < 2; i++) {
        int mAr = mb + i * 16 + qr, mBr = mAr + 8;
        int sA = slot_s[mAr], sB = slot_s[mBr];
        float gA = gate_s[mAr], gB = gate_s[mBr];
#pragma unroll
        for (int j = 0; j < 8; j++) {
            int c = nb2 + j * 8 + qc * 2;
            float2 b2 = *(const float2*)(fc2b + e * NCH + c);
            if (sA >= 0) {
                float2 o;
                o.x = gA * __expf(acc2[i][j][0] + b2.x);
                o.y = gA * __expf(acc2[i][j][1] + b2.y);
                *(float2*)(g_res + (size_t)sA * NCH + c) = o;
            }
            if (sB >= 0) {
                float2 o;
                o.x = gB * __expf(acc2[i][j][2] + b2.x);
                o.y = gB * __expf(acc2[i][j][3] + b2.y);
                *(float2*)(g_res + (size_t)sB * NCH + c) = o;
            }
        }
    }
}

// ---------------- kernel 5: combine + log + transpose back ----------------
__global__ void k_out(float* __restrict__ out) {
    __shared__ float tile[32][33];
    int bh = blockIdx.z;
    int b = bh / NH, h = bh % NH;
    int c0 = blockIdx.x * 32, w0 = blockIdx.y * 32;
    int tx = threadIdx.x, ty = threadIdx.y;
    for (int i = ty; i < 32; i += 8) {
        size_t base = (size_t)(b * NHW + h * NW + w0 + i) * 2 * NCH;
        float v = g_res[base + c0 + tx] + g_res[base + NCH + c0 + tx];
        if (v == 0.f) v = 2.2204460492503131e-16f;
        tile[i][tx] = logf(v);
    }
    __syncthreads();
    for (int i = ty; i < 32; i += 8)
        out[(((size_t)b * NCH + c0 + i) * NH + h) * NW + w0 + tx] = tile[tx][i];
}

// ---------------- launch ----------------
extern "C" void kernel_launch(void* const* d_in, const int* in_sizes, int n_in,
                              void* d_out, int out_size) {
    (void)in_sizes; (void)n_in;
    const float* x       = (const float*)d_in[0];
    const float* prompt  = (const float*)d_in[1];
    const float* de_cls  = (const float*)d_in[2];
    const float* w_g     = (const float*)d_in[3];
    const float* gboost  = (const float*)d_in[4];
    const float* degra_w = (const float*)d_in[5];
    const float* degra_b = (const float*)d_in[6];
    const float* fc1w    = (const float*)d_in[7];
    const float* fc1b    = (const float*)d_in[8];
    const float* fc2w    = (const float*)d_in[9];
    const float* fc2b    = (const float*)d_in[10];
    float* out = (float*)d_out;

    k_init<<<1, 32>>>();
    k_gate<<<GBLK, 256>>>(x, prompt, de_cls, w_g, gboost, degra_w, degra_b,
                          out, out_size);
    k_tp<<<TPBLK + 3072, 256>>>(x, fc1w, fc2w);

    cudaFuncSetAttribute(k_moe, cudaFuncAttributeMaxDynamicSharedMemorySize, S2_BYTES);
    k_moe<<<NE * 512, 256, S2_BYTES>>>(fc1b, fc2b);

    k_out<<<dim3(NCH / 32, NW / 32, NB * NH), dim3(32, 8)>>>(out);
}